// round 2
// baseline (speedup 1.0000x reference)
#include <cuda_runtime.h>

#define NODES_MAX 100000
#define IN_DIM 128
#define HIDDEN 128

// Scratch: per-node precomputed features. Y[n][0:128] = W1a @ z[n] (src part),
// Y[n][128:256] = W1b @ z[n] (dst part). 100000*256*4 = 102.4 MB.
__device__ float g_Y[(size_t)NODES_MAX * 256];
// Repacked weight: Wcat[k][o], k in [0,128) input dim, o in [0,256) output
// (o<128 -> src-half weights, o>=128 -> dst-half weights). Row-major [128][256].
__device__ float g_Wcat[IN_DIM * 256];
// 1 if edge_index is int64, 0 if int32.
__device__ int g_idx_is64;

// ---------------------------------------------------------------------------
// Kernel -1: detect index width. True int64 indices in [0,M) stay small;
// int32 data misread as int64 fuses adjacent pairs into huge values.
// ---------------------------------------------------------------------------
__global__ void detect_idx_kernel(const void* __restrict__ ei, int E, int M) {
    __shared__ int bad;
    if (threadIdx.x == 0) bad = 0;
    __syncthreads();
    const long long* p = (const long long*)ei;
    int n = E < 512 ? E : 512;
    for (int i = threadIdx.x; i < n; i += blockDim.x) {
        long long v = p[i];
        if (v < 0 || v >= (long long)M) atomicOr(&bad, 1);
    }
    __syncthreads();
    if (threadIdx.x == 0) g_idx_is64 = bad ? 0 : 1;
}

// ---------------------------------------------------------------------------
// Kernel 0: repack W1 (HIDDEN=128 rows x 256 cols, row-major) into Wcat.
// ---------------------------------------------------------------------------
__global__ void prep_wcat_kernel(const float* __restrict__ W1) {
    int i = blockIdx.x * blockDim.x + threadIdx.x;
    if (i < IN_DIM * 256) {
        int k = i >> 8;      // input dim 0..127
        int o = i & 255;     // output 0..255
        float v;
        if (o < HIDDEN)
            v = W1[o * (2 * IN_DIM) + k];                       // src half
        else
            v = W1[(o - HIDDEN) * (2 * IN_DIM) + IN_DIM + k];   // dst half
        g_Wcat[i] = v;
    }
}

// ---------------------------------------------------------------------------
// Kernel 1: node GEMM. Y[M x 256] = z[M x 128] @ Wcat[128 x 256].
// Tiling: BM=64, BN=64, BK=16; 256 threads; 4x4 register tile per thread.
// ---------------------------------------------------------------------------
__global__ void node_gemm_kernel(const float* __restrict__ z, int M) {
    __shared__ float As[64][16];   // [m][k]
    __shared__ float Bs[16][64];   // [k][n]

    const int tid = threadIdx.x;
    const int row0 = blockIdx.x * 64;
    const int col0 = blockIdx.y * 64;
    const int tx = tid & 15;   // n-direction (16 threads)
    const int ty = tid >> 4;   // m-direction (16 threads)

    float acc[4][4];
#pragma unroll
    for (int i = 0; i < 4; i++)
#pragma unroll
        for (int j = 0; j < 4; j++) acc[i][j] = 0.0f;

    // A-tile load mapping: 64 rows x 16 k = 256 float4; one float4 per thread.
    const int ar = tid >> 2;    // row within tile 0..63
    const int ac4 = tid & 3;    // which float4 of the 16-wide k slice
    // B-tile load mapping: 16 k x 64 n = 256 float4; one float4 per thread.
    const int br = tid >> 4;    // k row 0..15
    const int bc4 = tid & 15;   // float4 along n

    for (int kt = 0; kt < IN_DIM; kt += 16) {
        float4 av = make_float4(0.f, 0.f, 0.f, 0.f);
        int grow = row0 + ar;
        if (grow < M)
            av = *(const float4*)(z + (size_t)grow * IN_DIM + kt + ac4 * 4);
        *(float4*)&As[ar][ac4 * 4] = av;

        float4 bv = *(const float4*)(g_Wcat + (size_t)(kt + br) * 256 + col0 + bc4 * 4);
        *(float4*)&Bs[br][bc4 * 4] = bv;

        __syncthreads();

#pragma unroll
        for (int k = 0; k < 16; k++) {
            float a[4];
#pragma unroll
            for (int i = 0; i < 4; i++) a[i] = As[ty * 4 + i][k];
            float4 bb = *(const float4*)&Bs[k][tx * 4];
            float b[4] = {bb.x, bb.y, bb.z, bb.w};
#pragma unroll
            for (int i = 0; i < 4; i++)
#pragma unroll
                for (int j = 0; j < 4; j++)
                    acc[i][j] = fmaf(a[i], b[j], acc[i][j]);
        }
        __syncthreads();
    }

#pragma unroll
    for (int i = 0; i < 4; i++) {
        int grow = row0 + ty * 4 + i;
        if (grow < M) {
            float4 v0 = make_float4(acc[i][0], acc[i][1], acc[i][2], acc[i][3]);
            *(float4*)(g_Y + (size_t)grow * 256 + col0 + tx * 4) = v0;
        }
    }
}

// ---------------------------------------------------------------------------
// Kernel 2: per-edge stage. One warp per edge (grid-stride over edges).
// Lane l handles hidden units [4l, 4l+4): h = relu(A[src]+B[dst]+b1),
// partial dot with W2, warp-reduce, lane 0 writes out[e].
// ---------------------------------------------------------------------------
__global__ void edge_kernel(const void* __restrict__ ei,
                            const float* __restrict__ b1,
                            const float* __restrict__ W2,
                            const float* __restrict__ b2,
                            float* __restrict__ out, int E, int M) {
    const int lane = threadIdx.x & 31;
    int gw = (blockIdx.x * blockDim.x + threadIdx.x) >> 5;
    const int nw = (gridDim.x * blockDim.x) >> 5;

    const float4 b14 = *(const float4*)(b1 + lane * 4);
    const float4 w24 = *(const float4*)(W2 + lane * 4);
    const float b2v = b2[0];
    const int is64 = g_idx_is64;

    const long long* __restrict__ src64 = (const long long*)ei;
    const long long* __restrict__ dst64 = src64 + E;
    const int* __restrict__ src32 = (const int*)ei;
    const int* __restrict__ dst32 = src32 + E;

    for (int e = gw; e < E; e += nw) {
        int s, d;
        if (is64) {
            s = (int)src64[e];
            d = (int)dst64[e];
        } else {
            s = src32[e];
            d = dst32[e];
        }
        // Safety clamp: a wrong dtype guess degrades to rel_err, not IMA.
        if ((unsigned)s >= (unsigned)M) s = 0;
        if ((unsigned)d >= (unsigned)M) d = 0;

        float4 a  = *(const float4*)(g_Y + (size_t)s * 256 + lane * 4);
        float4 bb = *(const float4*)(g_Y + (size_t)d * 256 + 128 + lane * 4);

        float h0 = fmaxf(a.x + bb.x + b14.x, 0.0f);
        float h1 = fmaxf(a.y + bb.y + b14.y, 0.0f);
        float h2 = fmaxf(a.z + bb.z + b14.z, 0.0f);
        float h3 = fmaxf(a.w + bb.w + b14.w, 0.0f);

        float p = h0 * w24.x;
        p = fmaf(h1, w24.y, p);
        p = fmaf(h2, w24.z, p);
        p = fmaf(h3, w24.w, p);

#pragma unroll
        for (int o = 16; o > 0; o >>= 1)
            p += __shfl_xor_sync(0xffffffffu, p, o);

        if (lane == 0) out[e] = p + b2v;
    }
}

// ---------------------------------------------------------------------------
extern "C" void kernel_launch(void* const* d_in, const int* in_sizes, int n_in,
                              void* d_out, int out_size) {
    const float* z  = (const float*)d_in[0];
    const void*  ei = d_in[1];
    const float* W1 = (const float*)d_in[2];
    const float* b1 = (const float*)d_in[3];
    const float* W2 = (const float*)d_in[4];
    const float* b2 = (const float*)d_in[5];
    float*       out = (float*)d_out;

    int M = in_sizes[0] / IN_DIM;
    if (M > NODES_MAX) M = NODES_MAX;
    int E = in_sizes[1] / 2;

    detect_idx_kernel<<<1, 256>>>(ei, E, M);

    prep_wcat_kernel<<<(IN_DIM * 256 + 255) / 256, 256>>>(W1);

    dim3 ggrid((M + 63) / 64, 256 / 64);
    node_gemm_kernel<<<ggrid, 256>>>(z, M);

    edge_kernel<<<1184, 256>>>(ei, b1, W2, b2, out, E, M);
}

// round 5
// speedup vs baseline: 1.3557x; 1.3557x over previous
#include <cuda_runtime.h>
#include <cuda_bf16.h>
#include <cstdint>

#define NODES_MAX 100000
#define M_PAD 100096            // round up to 128
#define IN_DIM 128
#define HIDDEN 128
#define KEFF 384                // 3 x 128 (hi*hi, lo*hi, hi*lo)
#define NCHUNK 12               // KEFF / 32

// Scratch (device globals: no allocations allowed).
__device__ float g_Y[(size_t)M_PAD * 256];                 // per-node [A|B] features
__device__ __nv_bfloat16 g_Apack[(size_t)M_PAD * 256];     // [z_hi | z_lo]
__device__ __nv_bfloat16 g_Bpack[KEFF * 256];              // [W_hi; W_hi; W_lo]
__device__ int g_idx_is64;

// ---------------------------------------------------------------------------
// Detect index width (int64 vs int32 read as int64).
// ---------------------------------------------------------------------------
__global__ void detect_idx_kernel(const void* __restrict__ ei, int E, int M) {
    __shared__ int bad;
    if (threadIdx.x == 0) bad = 0;
    __syncthreads();
    const long long* p = (const long long*)ei;
    int n = E < 512 ? E : 512;
    for (int i = threadIdx.x; i < n; i += blockDim.x) {
        long long v = p[i];
        if (v < 0 || v >= (long long)M) atomicOr(&bad, 1);
    }
    __syncthreads();
    if (threadIdx.x == 0) g_idx_is64 = bad ? 0 : 1;
}

// ---------------------------------------------------------------------------
// Split z into bf16 hi/lo -> Apack[M][256] = [hi(128) | lo(128)]
// ---------------------------------------------------------------------------
__global__ void prep_apack(const float* __restrict__ z, int M) {
    int i = blockIdx.x * blockDim.x + threadIdx.x;
    if (i < M * IN_DIM) {
        int r = i >> 7, c = i & 127;
        float v = z[i];
        __nv_bfloat16 hi = __float2bfloat16(v);
        __nv_bfloat16 lo = __float2bfloat16(v - __bfloat162float(hi));
        g_Apack[(size_t)r * 256 + c] = hi;
        g_Apack[(size_t)r * 256 + 128 + c] = lo;
    }
}

// ---------------------------------------------------------------------------
// Split W1 (repacked to [k][o], o<128 src half / o>=128 dst half) into
// Bpack rows: [0,128)=hi, [128,256)=hi, [256,384)=lo.
// A cols: [0,256)->k natural ([hi|lo]); seg2 reuses hi (a_col = k-256).
// => products hi*hi, lo*hi, hi*lo.
// ---------------------------------------------------------------------------
__global__ void prep_bpack(const float* __restrict__ W1) {
    int i = blockIdx.x * blockDim.x + threadIdx.x;
    if (i < IN_DIM * 256) {
        int k = i >> 8, o = i & 255;
        float v = (o < HIDDEN) ? W1[o * (2 * IN_DIM) + k]
                               : W1[(o - HIDDEN) * (2 * IN_DIM) + IN_DIM + k];
        __nv_bfloat16 hi = __float2bfloat16(v);
        __nv_bfloat16 lo = __float2bfloat16(v - __bfloat162float(hi));
        g_Bpack[k * 256 + o] = hi;
        g_Bpack[(128 + k) * 256 + o] = hi;
        g_Bpack[(256 + k) * 256 + o] = lo;
    }
}

// ---------------------------------------------------------------------------
// Tensor-core GEMM: Y[M x 256] = Apack(view) [M x 384] @ Bpack [384 x 256].
// CTA tile 128x128, 8 warps (2m x 4n of 64x32), KC=32, double-buffered smem,
// ldmatrix + mma.sync.m16n8k16 bf16 -> fp32.
// ---------------------------------------------------------------------------
__device__ __forceinline__ void ldsm4(uint32_t* r, uint32_t addr) {
    asm volatile("ldmatrix.sync.aligned.m8n8.x4.shared.b16 {%0,%1,%2,%3}, [%4];"
                 : "=r"(r[0]), "=r"(r[1]), "=r"(r[2]), "=r"(r[3]) : "r"(addr));
}
__device__ __forceinline__ void ldsm4t(uint32_t* r, uint32_t addr) {
    asm volatile("ldmatrix.sync.aligned.m8n8.x4.trans.shared.b16 {%0,%1,%2,%3}, [%4];"
                 : "=r"(r[0]), "=r"(r[1]), "=r"(r[2]), "=r"(r[3]) : "r"(addr));
}
#define MMA16816(d, a, b)                                                      \
    asm volatile(                                                              \
        "mma.sync.aligned.m16n8k16.row.col.f32.bf16.bf16.f32 "                 \
        "{%0,%1,%2,%3}, {%4,%5,%6,%7}, {%8,%9}, {%0,%1,%2,%3};"                \
        : "+f"(d[0]), "+f"(d[1]), "+f"(d[2]), "+f"(d[3])                       \
        : "r"(a[0]), "r"(a[1]), "r"(a[2]), "r"(a[3]), "r"(b[0]), "r"(b[1]))

__global__ __launch_bounds__(256, 2) void node_gemm_bf16(int M) {
    // buffer: A tile 128x32 bf16 = 8KB at +0; B tile 32x128 bf16 = 8KB at +8192
    __shared__ __align__(16) unsigned char smem[2][16384];

    const int tid = threadIdx.x;
    const int lane = tid & 31;
    const int w = tid >> 5;
    const int wm = w & 1;          // 2 warps along M (64 each)
    const int wn = w >> 1;         // 4 warps along N (32 each)
    const int row0 = blockIdx.x * 128;
    const int col0 = blockIdx.y * 128;

    // --- global->smem load mapping ---
    const int ar = tid >> 1;       // A row 0..127
    const int ac = tid & 1;        // A 16B slots {ac, ac+2} of 4
    const int bk = tid >> 3;       // B row 0..31
    const int bs = tid & 7;        // B 16B slots {bs, bs+8} of 16

    // smem byte offsets (with swizzles)
    const int sA0 = ar * 64 + (((ac)     ^ ((ar >> 1) & 3)) << 4);
    const int sA1 = ar * 64 + (((ac + 2) ^ ((ar >> 1) & 3)) << 4);
    const int sB0 = 8192 + bk * 256 + (((bs)     << 4) ^ ((bk & 7) << 4));
    const int sB1 = 8192 + bk * 256 + (((bs + 8) << 4) ^ ((bk & 7) << 4));

    // --- ldmatrix per-thread addresses (offsets within a buffer) ---
    uint32_t aOff[4], bOff[2];
#pragma unroll
    for (int mi = 0; mi < 4; mi++) {
        int r = wm * 64 + mi * 16 + (lane & 15);
        int slot = (lane >> 4) ^ ((r >> 1) & 3);
        aOff[mi] = r * 64 + slot * 16;            // kk=16 -> ^0x20
    }
    {
        int k = lane & 15;
#pragma unroll
        for (int ni = 0; ni < 2; ni++) {
            int nb = wn * 64 + ni * 32 + ((lane >> 4) & 1) * 16;
            bOff[ni] = 8192 + k * 256 + (nb ^ ((k & 7) << 4)); // kk=16 -> +4096
        }
    }
    const uint32_t sbase = (uint32_t)__cvta_generic_to_shared(&smem[0][0]);

    float acc[4][4][4];
#pragma unroll
    for (int i = 0; i < 4; i++)
#pragma unroll
        for (int j = 0; j < 4; j++)
#pragma unroll
            for (int t = 0; t < 4; t++) acc[i][j][t] = 0.0f;

    const __nv_bfloat16* Ag = g_Apack + (size_t)(row0 + ar) * 256;

    // prologue: chunk 0
    uint4 ra0, ra1, rb0, rb1;
    {
        ra0 = *(const uint4*)(Ag + ac * 8);
        ra1 = *(const uint4*)(Ag + ac * 8 + 16);
        const __nv_bfloat16* Bg = g_Bpack + (size_t)bk * 256 + col0;
        rb0 = *(const uint4*)(Bg + bs * 8);
        rb1 = *(const uint4*)(Bg + bs * 8 + 64);
        *(uint4*)(&smem[0][0] + sA0) = ra0;
        *(uint4*)(&smem[0][0] + sA1) = ra1;
        *(uint4*)(&smem[0][0] + sB0) = rb0;
        *(uint4*)(&smem[0][0] + sB1) = rb1;
    }
    __syncthreads();

    for (int c = 0; c < NCHUNK; c++) {
        const int cur = c & 1;
        const uint32_t buf = sbase + cur * 16384;

        if (c + 1 < NCHUNK) {
            int k0 = (c + 1) * 32;
            int ca = (k0 < 256) ? k0 : (k0 - 256);
            ra0 = *(const uint4*)(Ag + ca + ac * 8);
            ra1 = *(const uint4*)(Ag + ca + ac * 8 + 16);
            const __nv_bfloat16* Bg = g_Bpack + (size_t)(k0 + bk) * 256 + col0;
            rb0 = *(const uint4*)(Bg + bs * 8);
            rb1 = *(const uint4*)(Bg + bs * 8 + 64);
        }

#pragma unroll
        for (int kk = 0; kk < 2; kk++) {
            uint32_t a[4][4], b[4][2];
#pragma unroll
            for (int mi = 0; mi < 4; mi++)
                ldsm4(a[mi], buf + (kk ? (aOff[mi] ^ 0x20) : aOff[mi]));
#pragma unroll
            for (int ni = 0; ni < 2; ni++) {
                uint32_t r[4];
                ldsm4t(r, buf + bOff[ni] + (kk ? 4096 : 0));
                b[ni * 2 + 0][0] = r[0]; b[ni * 2 + 0][1] = r[1];
                b[ni * 2 + 1][0] = r[2]; b[ni * 2 + 1][1] = r[3];
            }
#pragma unroll
            for (int mi = 0; mi < 4; mi++)
#pragma unroll
                for (int ni = 0; ni < 4; ni++)
                    MMA16816(acc[mi][ni], a[mi], b[ni]);
        }

        if (c + 1 < NCHUNK) {
            unsigned char* nb = &smem[cur ^ 1][0];
            *(uint4*)(nb + sA0) = ra0;
            *(uint4*)(nb + sA1) = ra1;
            *(uint4*)(nb + sB0) = rb0;
            *(uint4*)(nb + sB1) = rb1;
            __syncthreads();
        }
    }

    // epilogue
    const int tr = lane >> 2;
    const int tc = (lane & 3) * 2;
#pragma unroll
    for (int mi = 0; mi < 4; mi++) {
#pragma unroll
        for (int ni = 0; ni < 4; ni++) {
            int gr = row0 + wm * 64 + mi * 16 + tr;
            int gc = col0 + wn * 32 + ni * 8 + tc;
            if (gr < M) {
                float2 v0 = make_float2(acc[mi][ni][0], acc[mi][ni][1]);
                *(float2*)(g_Y + (size_t)gr * 256 + gc) = v0;
            }
            if (gr + 8 < M) {
                float2 v1 = make_float2(acc[mi][ni][2], acc[mi][ni][3]);
                *(float2*)(g_Y + (size_t)(gr + 8) * 256 + gc) = v1;
            }
        }
    }
}

// ---------------------------------------------------------------------------
// Per-edge stage: one warp per edge; lane l handles hidden units [4l,4l+4).
// ---------------------------------------------------------------------------
__global__ void edge_kernel(const void* __restrict__ ei,
                            const float* __restrict__ b1,
                            const float* __restrict__ W2,
                            const float* __restrict__ b2,
                            float* __restrict__ out, int E, int M) {
    const int lane = threadIdx.x & 31;
    int gw = (blockIdx.x * blockDim.x + threadIdx.x) >> 5;
    const int nw = (gridDim.x * blockDim.x) >> 5;

    const float4 b14 = *(const float4*)(b1 + lane * 4);
    const float4 w24 = *(const float4*)(W2 + lane * 4);
    const float b2v = b2[0];
    const int is64 = g_idx_is64;

    const long long* __restrict__ src64 = (const long long*)ei;
    const long long* __restrict__ dst64 = src64 + E;
    const int* __restrict__ src32 = (const int*)ei;
    const int* __restrict__ dst32 = src32 + E;

    for (int e = gw; e < E; e += nw) {
        int s, d;
        if (is64) { s = (int)src64[e]; d = (int)dst64[e]; }
        else      { s = src32[e];      d = dst32[e]; }
        if ((unsigned)s >= (unsigned)M) s = 0;
        if ((unsigned)d >= (unsigned)M) d = 0;

        float4 a  = *(const float4*)(g_Y + (size_t)s * 256 + lane * 4);
        float4 bb = *(const float4*)(g_Y + (size_t)d * 256 + 128 + lane * 4);

        float h0 = fmaxf(a.x + bb.x + b14.x, 0.0f);
        float h1 = fmaxf(a.y + bb.y + b14.y, 0.0f);
        float h2 = fmaxf(a.z + bb.z + b14.z, 0.0f);
        float h3 = fmaxf(a.w + bb.w + b14.w, 0.0f);

        float p = h0 * w24.x;
        p = fmaf(h1, w24.y, p);
        p = fmaf(h2, w24.z, p);
        p = fmaf(h3, w24.w, p);

#pragma unroll
        for (int o = 16; o > 0; o >>= 1)
            p += __shfl_xor_sync(0xffffffffu, p, o);

        if (lane == 0) out[e] = p + b2v;
    }
}

// ---------------------------------------------------------------------------
extern "C" void kernel_launch(void* const* d_in, const int* in_sizes, int n_in,
                              void* d_out, int out_size) {
    const float* z  = (const float*)d_in[0];
    const void*  ei = d_in[1];
    const float* W1 = (const float*)d_in[2];
    const float* b1 = (const float*)d_in[3];
    const float* W2 = (const float*)d_in[4];
    const float* b2 = (const float*)d_in[5];
    float*       out = (float*)d_out;

    int M = in_sizes[0] / IN_DIM;
    if (M > NODES_MAX) M = NODES_MAX;
    int E = in_sizes[1] / 2;

    detect_idx_kernel<<<1, 256>>>(ei, E, M);
    prep_apack<<<(M * IN_DIM + 255) / 256, 256>>>(z, M);
    prep_bpack<<<(IN_DIM * 256 + 255) / 256, 256>>>(W1);

    dim3 ggrid(M_PAD / 128, 2);
    node_gemm_bf16<<<ggrid, 256>>>(M);

    edge_kernel<<<1184, 256>>>(ei, b1, W2, b2, out, E, M);
}

// round 6
// speedup vs baseline: 1.5361x; 1.1331x over previous
#include <cuda_runtime.h>
#include <cuda_fp16.h>
#include <cstdint>

#define NODES_MAX 100000
#define M_PAD 100096            // round up to 128
#define IN_DIM 128
#define HIDDEN 128
#define NCHUNK 4                // K=128 / 32

// Scratch (device globals: no allocations allowed).
__device__ __half g_Yh[(size_t)M_PAD * 256];     // per-node [A|B] features, fp16 (51 MB, L2-resident)
__device__ __half g_Zh[(size_t)M_PAD * 128];     // z in fp16
__device__ __half g_Wh[IN_DIM * 256];            // repacked W1 [k][o] fp16
__device__ int g_idx_is64;

// ---------------------------------------------------------------------------
// Detect index width (int64 vs int32 read as int64).
// ---------------------------------------------------------------------------
__global__ void detect_idx_kernel(const void* __restrict__ ei, int E, int M) {
    __shared__ int bad;
    if (threadIdx.x == 0) bad = 0;
    __syncthreads();
    const long long* p = (const long long*)ei;
    int n = E < 512 ? E : 512;
    for (int i = threadIdx.x; i < n; i += blockDim.x) {
        long long v = p[i];
        if (v < 0 || v >= (long long)M) atomicOr(&bad, 1);
    }
    __syncthreads();
    if (threadIdx.x == 0) g_idx_is64 = bad ? 0 : 1;
}

// ---------------------------------------------------------------------------
// z (fp32) -> fp16, vectorized 4 elements/thread.
// ---------------------------------------------------------------------------
__global__ void prep_z(const float* __restrict__ z, int M) {
    int i = blockIdx.x * blockDim.x + threadIdx.x;   // float4 index
    int n4 = (M * IN_DIM) >> 2;
    if (i < n4) {
        float4 v = ((const float4*)z)[i];
        __half2 h0 = __floats2half2_rn(v.x, v.y);
        __half2 h1 = __floats2half2_rn(v.z, v.w);
        ((__half2*)g_Zh)[i * 2 + 0] = h0;
        ((__half2*)g_Zh)[i * 2 + 1] = h1;
    }
}

// ---------------------------------------------------------------------------
// Repack W1 (HIDDEN x 2*IN_DIM row-major) into Wh[k][o] fp16:
// o<128 -> src-half weights, o>=128 -> dst-half weights.
// ---------------------------------------------------------------------------
__global__ void prep_w(const float* __restrict__ W1) {
    int i = blockIdx.x * blockDim.x + threadIdx.x;
    if (i < IN_DIM * 256) {
        int k = i >> 8, o = i & 255;
        float v = (o < HIDDEN) ? W1[o * (2 * IN_DIM) + k]
                               : W1[(o - HIDDEN) * (2 * IN_DIM) + IN_DIM + k];
        g_Wh[i] = __float2half_rn(v);
    }
}

// ---------------------------------------------------------------------------
// Tensor-core GEMM: Yh[M x 256] = Zh[M x 128] @ Wh[128 x 256], fp16 in/out,
// fp32 accumulate. CTA tile 128x128, 8 warps (2m x 4n of 64x32), KC=32,
// double-buffered smem, ldmatrix + mma.sync.m16n8k16.
// ---------------------------------------------------------------------------
__device__ __forceinline__ void ldsm4(uint32_t* r, uint32_t addr) {
    asm volatile("ldmatrix.sync.aligned.m8n8.x4.shared.b16 {%0,%1,%2,%3}, [%4];"
                 : "=r"(r[0]), "=r"(r[1]), "=r"(r[2]), "=r"(r[3]) : "r"(addr));
}
__device__ __forceinline__ void ldsm4t(uint32_t* r, uint32_t addr) {
    asm volatile("ldmatrix.sync.aligned.m8n8.x4.trans.shared.b16 {%0,%1,%2,%3}, [%4];"
                 : "=r"(r[0]), "=r"(r[1]), "=r"(r[2]), "=r"(r[3]) : "r"(addr));
}
#define MMA16816(d, a, b)                                                      \
    asm volatile(                                                              \
        "mma.sync.aligned.m16n8k16.row.col.f32.f16.f16.f32 "                   \
        "{%0,%1,%2,%3}, {%4,%5,%6,%7}, {%8,%9}, {%0,%1,%2,%3};"                \
        : "+f"(d[0]), "+f"(d[1]), "+f"(d[2]), "+f"(d[3])                       \
        : "r"(a[0]), "r"(a[1]), "r"(a[2]), "r"(a[3]), "r"(b[0]), "r"(b[1]))

__global__ __launch_bounds__(256, 2) void node_gemm_f16(int M) {
    // per buffer: A tile 128x32 f16 = 8KB at +0; B tile 32x128 f16 = 8KB at +8192
    __shared__ __align__(16) unsigned char smem[2][16384];

    const int tid = threadIdx.x;
    const int lane = tid & 31;
    const int w = tid >> 5;
    const int wm = w & 1;          // 2 warps along M (64 each)
    const int wn = w >> 1;         // 4 warps along N (32 each)
    const int row0 = blockIdx.x * 128;
    const int col0 = blockIdx.y * 128;

    // --- global->smem load mapping ---
    const int ar = tid >> 1;       // A row 0..127 (64B per row per chunk)
    const int ac = tid & 1;        // A 16B slots {ac, ac+2} of 4
    const int bk = tid >> 3;       // B row 0..31 (256B per row)
    const int bs = tid & 7;        // B 16B slots {bs, bs+8} of 16

    // smem byte offsets (with swizzles)
    const int sA0 = ar * 64 + (((ac)     ^ ((ar >> 1) & 3)) << 4);
    const int sA1 = ar * 64 + (((ac + 2) ^ ((ar >> 1) & 3)) << 4);
    const int sB0 = 8192 + bk * 256 + (((bs)     << 4) ^ ((bk & 7) << 4));
    const int sB1 = 8192 + bk * 256 + (((bs + 8) << 4) ^ ((bk & 7) << 4));

    // --- ldmatrix per-thread addresses (offsets within a buffer) ---
    uint32_t aOff[4], bOff[2];
#pragma unroll
    for (int mi = 0; mi < 4; mi++) {
        int r = wm * 64 + mi * 16 + (lane & 15);
        int slot = (lane >> 4) ^ ((r >> 1) & 3);
        aOff[mi] = r * 64 + slot * 16;            // kk=16 -> ^0x20
    }
    {
        int k = lane & 15;
#pragma unroll
        for (int ni = 0; ni < 2; ni++) {
            int nb = wn * 64 + ni * 32 + ((lane >> 4) & 1) * 16;
            bOff[ni] = 8192 + k * 256 + (nb ^ ((k & 7) << 4)); // kk=16 -> +4096
        }
    }
    const uint32_t sbase = (uint32_t)__cvta_generic_to_shared(&smem[0][0]);

    float acc[4][4][4];
#pragma unroll
    for (int i = 0; i < 4; i++)
#pragma unroll
        for (int j = 0; j < 4; j++)
#pragma unroll
            for (int t = 0; t < 4; t++) acc[i][j][t] = 0.0f;

    const __half* Ag = g_Zh + (size_t)(row0 + ar) * 128;

    // prologue: chunk 0
    uint4 ra0, ra1, rb0, rb1;
    {
        ra0 = *(const uint4*)(Ag + ac * 8);
        ra1 = *(const uint4*)(Ag + ac * 8 + 16);
        const __half* Bg = g_Wh + (size_t)bk * 256 + col0;
        rb0 = *(const uint4*)(Bg + bs * 8);
        rb1 = *(const uint4*)(Bg + bs * 8 + 64);
        *(uint4*)(&smem[0][0] + sA0) = ra0;
        *(uint4*)(&smem[0][0] + sA1) = ra1;
        *(uint4*)(&smem[0][0] + sB0) = rb0;
        *(uint4*)(&smem[0][0] + sB1) = rb1;
    }
    __syncthreads();

    for (int c = 0; c < NCHUNK; c++) {
        const int cur = c & 1;
        const uint32_t buf = sbase + cur * 16384;

        if (c + 1 < NCHUNK) {
            int k0 = (c + 1) * 32;
            ra0 = *(const uint4*)(Ag + k0 + ac * 8);
            ra1 = *(const uint4*)(Ag + k0 + ac * 8 + 16);
            const __half* Bg = g_Wh + (size_t)(k0 + bk) * 256 + col0;
            rb0 = *(const uint4*)(Bg + bs * 8);
            rb1 = *(const uint4*)(Bg + bs * 8 + 64);
        }

#pragma unroll
        for (int kk = 0; kk < 2; kk++) {
            uint32_t a[4][4], b[4][2];
#pragma unroll
            for (int mi = 0; mi < 4; mi++)
                ldsm4(a[mi], buf + (kk ? (aOff[mi] ^ 0x20) : aOff[mi]));
#pragma unroll
            for (int ni = 0; ni < 2; ni++) {
                uint32_t r[4];
                ldsm4t(r, buf + bOff[ni] + (kk ? 4096 : 0));
                b[ni * 2 + 0][0] = r[0]; b[ni * 2 + 0][1] = r[1];
                b[ni * 2 + 1][0] = r[2]; b[ni * 2 + 1][1] = r[3];
            }
#pragma unroll
            for (int mi = 0; mi < 4; mi++)
#pragma unroll
                for (int ni = 0; ni < 4; ni++)
                    MMA16816(acc[mi][ni], a[mi], b[ni]);
        }

        if (c + 1 < NCHUNK) {
            unsigned char* nb = &smem[cur ^ 1][0];
            *(uint4*)(nb + sA0) = ra0;
            *(uint4*)(nb + sA1) = ra1;
            *(uint4*)(nb + sB0) = rb0;
            *(uint4*)(nb + sB1) = rb1;
            __syncthreads();
        }
    }

    // epilogue: fp32 acc -> fp16 Y
    const int tr = lane >> 2;
    const int tc = (lane & 3) * 2;
#pragma unroll
    for (int mi = 0; mi < 4; mi++) {
#pragma unroll
        for (int ni = 0; ni < 4; ni++) {
            int gr = row0 + wm * 64 + mi * 16 + tr;
            int gc = col0 + wn * 32 + ni * 8 + tc;
            if (gr < M) {
                __half2 v0 = __floats2half2_rn(acc[mi][ni][0], acc[mi][ni][1]);
                *(__half2*)(g_Yh + (size_t)gr * 256 + gc) = v0;
            }
            if (gr + 8 < M) {
                __half2 v1 = __floats2half2_rn(acc[mi][ni][2], acc[mi][ni][3]);
                *(__half2*)(g_Yh + (size_t)(gr + 8) * 256 + gc) = v1;
            }
        }
    }
}

// ---------------------------------------------------------------------------
// Per-edge stage: one warp per edge; lane l handles hidden units [4l,4l+4).
// Y is fp16 -> half the gather traffic; fp32 math after load.
// ---------------------------------------------------------------------------
__global__ void edge_kernel(const void* __restrict__ ei,
                            const float* __restrict__ b1,
                            const float* __restrict__ W2,
                            const float* __restrict__ b2,
                            float* __restrict__ out, int E, int M) {
    const int lane = threadIdx.x & 31;
    int gw = (blockIdx.x * blockDim.x + threadIdx.x) >> 5;
    const int nw = (gridDim.x * blockDim.x) >> 5;

    const float4 b14 = *(const float4*)(b1 + lane * 4);
    const float4 w24 = *(const float4*)(W2 + lane * 4);
    const float b2v = b2[0];
    const int is64 = g_idx_is64;

    const long long* __restrict__ src64 = (const long long*)ei;
    const long long* __restrict__ dst64 = src64 + E;
    const int* __restrict__ src32 = (const int*)ei;
    const int* __restrict__ dst32 = src32 + E;

    for (int e = gw; e < E; e += nw) {
        int s, d;
        if (is64) { s = (int)src64[e]; d = (int)dst64[e]; }
        else      { s = src32[e];      d = dst32[e]; }
        if ((unsigned)s >= (unsigned)M) s = 0;
        if ((unsigned)d >= (unsigned)M) d = 0;

        uint2 av = *(const uint2*)(g_Yh + (size_t)s * 256 + lane * 4);
        uint2 bv = *(const uint2*)(g_Yh + (size_t)d * 256 + 128 + lane * 4);

        float2 a01 = __half22float2(*(__half2*)&av.x);
        float2 a23 = __half22float2(*(__half2*)&av.y);
        float2 c01 = __half22float2(*(__half2*)&bv.x);
        float2 c23 = __half22float2(*(__half2*)&bv.y);

        float h0 = fmaxf(a01.x + c01.x + b14.x, 0.0f);
        float h1 = fmaxf(a01.y + c01.y + b14.y, 0.0f);
        float h2 = fmaxf(a23.x + c23.x + b14.z, 0.0f);
        float h3 = fmaxf(a23.y + c23.y + b14.w, 0.0f);

        float p = h0 * w24.x;
        p = fmaf(h1, w24.y, p);
        p = fmaf(h2, w24.z, p);
        p = fmaf(h3, w24.w, p);

#pragma unroll
        for (int o = 16; o > 0; o >>= 1)
            p += __shfl_xor_sync(0xffffffffu, p, o);

        if (lane == 0) out[e] = p + b2v;
    }
}

// ---------------------------------------------------------------------------
extern "C" void kernel_launch(void* const* d_in, const int* in_sizes, int n_in,
                              void* d_out, int out_size) {
    const float* z  = (const float*)d_in[0];
    const void*  ei = d_in[1];
    const float* W1 = (const float*)d_in[2];
    const float* b1 = (const float*)d_in[3];
    const float* W2 = (const float*)d_in[4];
    const float* b2 = (const float*)d_in[5];
    float*       out = (float*)d_out;

    int M = in_sizes[0] / IN_DIM;
    if (M > NODES_MAX) M = NODES_MAX;
    int E = in_sizes[1] / 2;

    detect_idx_kernel<<<1, 256>>>(ei, E, M);
    prep_z<<<((M * IN_DIM / 4) + 255) / 256, 256>>>(z, M);
    prep_w<<<(IN_DIM * 256 + 255) / 256, 256>>>(W1);

    dim3 ggrid(M_PAD / 128, 2);
    node_gemm_f16<<<ggrid, 256>>>(M);

    edge_kernel<<<1184, 256>>>(ei, b1, W2, b2, out, E, M);
}

// round 8
// speedup vs baseline: 1.9916x; 1.2965x over previous
#include <cuda_runtime.h>
#include <cuda_fp16.h>
#include <cstdint>

#define NODES_MAX 100000
#define M_PAD 100096            // round up to 128
#define IN_DIM 128
#define HIDDEN 128

// Scratch (device globals: no allocations allowed).
__device__ __half g_Yh[(size_t)M_PAD * 256];     // per-node [A|B] features, fp16 (51 MB)
__device__ __half g_Zh[(size_t)M_PAD * 128];     // z in fp16
__device__ __half g_Wh[IN_DIM * 256];            // repacked W1 [k][o] fp16
__device__ int g_idx_is64;

// ---------------------------------------------------------------------------
// Detect index width (int64 vs int32 read as int64).
// ---------------------------------------------------------------------------
__global__ void detect_idx_kernel(const void* __restrict__ ei, int E, int M) {
    __shared__ int bad;
    if (threadIdx.x == 0) bad = 0;
    __syncthreads();
    const long long* p = (const long long*)ei;
    int n = E < 512 ? E : 512;
    for (int i = threadIdx.x; i < n; i += blockDim.x) {
        long long v = p[i];
        if (v < 0 || v >= (long long)M) atomicOr(&bad, 1);
    }
    __syncthreads();
    if (threadIdx.x == 0) g_idx_is64 = bad ? 0 : 1;
}

// ---------------------------------------------------------------------------
// z (fp32) -> fp16.
// ---------------------------------------------------------------------------
__global__ void prep_z(const float* __restrict__ z, int M) {
    int i = blockIdx.x * blockDim.x + threadIdx.x;   // float4 index
    int n4 = (M * IN_DIM) >> 2;
    if (i < n4) {
        float4 v = ((const float4*)z)[i];
        ((__half2*)g_Zh)[i * 2 + 0] = __floats2half2_rn(v.x, v.y);
        ((__half2*)g_Zh)[i * 2 + 1] = __floats2half2_rn(v.z, v.w);
    }
}

// ---------------------------------------------------------------------------
// Repack W1 (HIDDEN x 2*IN_DIM row-major) into Wh[k][o] fp16.
// ---------------------------------------------------------------------------
__global__ void prep_w(const float* __restrict__ W1) {
    int i = blockIdx.x * blockDim.x + threadIdx.x;
    if (i < IN_DIM * 256) {
        int k = i >> 8, o = i & 255;
        float v = (o < HIDDEN) ? W1[o * (2 * IN_DIM) + k]
                               : W1[(o - HIDDEN) * (2 * IN_DIM) + IN_DIM + k];
        g_Wh[i] = __float2half_rn(v);
    }
}

// ---------------------------------------------------------------------------
// GEMM helpers.
// ---------------------------------------------------------------------------
__device__ __forceinline__ void ldsm4(uint32_t* r, uint32_t addr) {
    asm volatile("ldmatrix.sync.aligned.m8n8.x4.shared.b16 {%0,%1,%2,%3}, [%4];"
                 : "=r"(r[0]), "=r"(r[1]), "=r"(r[2]), "=r"(r[3]) : "r"(addr));
}
__device__ __forceinline__ void ldsm4t(uint32_t* r, uint32_t addr) {
    asm volatile("ldmatrix.sync.aligned.m8n8.x4.trans.shared.b16 {%0,%1,%2,%3}, [%4];"
                 : "=r"(r[0]), "=r"(r[1]), "=r"(r[2]), "=r"(r[3]) : "r"(addr));
}
__device__ __forceinline__ void cp16(uint32_t saddr, const void* gptr) {
    asm volatile("cp.async.cg.shared.global [%0], [%1], 16;" :: "r"(saddr), "l"(gptr));
}
__device__ __forceinline__ void cp_commit() {
    asm volatile("cp.async.commit_group;");
}
template <int N> __device__ __forceinline__ void cp_wait() {
    asm volatile("cp.async.wait_group %0;" :: "n"(N));
}
#define MMA16816(d, a, b)                                                      \
    asm volatile(                                                              \
        "mma.sync.aligned.m16n8k16.row.col.f32.f16.f16.f32 "                   \
        "{%0,%1,%2,%3}, {%4,%5,%6,%7}, {%8,%9}, {%0,%1,%2,%3};"                \
        : "+f"(d[0]), "+f"(d[1]), "+f"(d[2]), "+f"(d[3])                       \
        : "r"(a[0]), "r"(a[1]), "r"(a[2]), "r"(a[3]), "r"(b[0]), "r"(b[1]))

// ---------------------------------------------------------------------------
// Tensor-core GEMM: Yh[M x 256] = Zh[M x 128] @ Wh[128 x 256].
// CTA tile 64x128, 8 warps (2m x 4n of 32x32). K=128 as 4 chunks of 32, all
// 4 stages cp.async-prefetched up front (distinct buffers -> no WAR hazard),
// one wait_group + syncthreads per chunk.
// Stage layout (12KB): A 64rows x 64B at +0; B 32krows x 256B at +4096.
// Swizzle family identical to the validated R6 kernel:
//   store A: slot s (16B) of row r at byte r*64 + ((s ^ ((r>>1)&3))<<4)
//   store B: slot s (16B) of krow k at byte k*256 + ((s<<4) ^ ((k&7)<<4))
//   load  A: chunk c = (lane>>4)+2*kk -> byte r*64 + ((c ^ ((r>>1)&3))<<4)
//            (kk=1 via ^0x20 since c<2 for kk=0)
//   load  B: nb = wn*64 + ni*32 + ((lane>>4)&1)*16, k=lane&15 (+16 via +4096)
//            byte 4096 + k*256 + (nb ^ ((k&7)<<4))
// ---------------------------------------------------------------------------
#define STAGE_BYTES 12288

__global__ __launch_bounds__(256, 3) void node_gemm_f16(int M) {
    __shared__ __align__(16) unsigned char smem[4 * STAGE_BYTES];

    const int tid = threadIdx.x;
    const int lane = tid & 31;
    const int w = tid >> 5;
    const int wm = w & 1;          // 2 warps along M (32 rows each)
    const int wn = w >> 1;         // 4 warps along N (32 cols each)
    const int row0 = blockIdx.x * 64;
    const int col0 = blockIdx.y * 128;

    const uint32_t sbase = (uint32_t)__cvta_generic_to_shared(&smem[0]);

    // ---- async store mappings ----
    // A: 64 rows x 64B; thread t -> row=t>>2, 16B slot=t&3.
    const int ar = tid >> 2;
    const int as = tid & 3;
    const uint32_t sA = sbase + ar * 64 + (((as) ^ ((ar >> 1) & 3)) << 4);
    const __half* AgBase = g_Zh + (size_t)(row0 + ar) * 128 + as * 8;
    // B: 32 k-rows x 256B; thread t -> k=t>>3, 16B slots {bs, bs+8}.
    const int bk = tid >> 3;
    const int bs = tid & 7;
    const uint32_t sB0 = sbase + 4096 + bk * 256 + (((bs) << 4) ^ ((bk & 7) << 4));
    const uint32_t sB1 = sbase + 4096 + bk * 256 + (((bs + 8) << 4) ^ ((bk & 7) << 4));
    const __half* BgBase = g_Wh + (size_t)bk * 256 + col0 + bs * 8;

    // Issue all 4 stages (one commit group per k-chunk).
#pragma unroll
    for (int c = 0; c < 4; c++) {
        uint32_t st = c * STAGE_BYTES;
        cp16(sA + st, AgBase + c * 32);
        cp16(sB0 + st, BgBase + (size_t)c * 32 * 256);
        cp16(sB1 + st, BgBase + (size_t)c * 32 * 256 + 64);
        cp_commit();
    }

    // ---- ldmatrix per-thread offsets (within a stage) ----
    uint32_t aOff[2];
#pragma unroll
    for (int mi = 0; mi < 2; mi++) {
        int r = wm * 32 + mi * 16 + (lane & 15);
        int slot = (lane >> 4) ^ ((r >> 1) & 3);
        aOff[mi] = r * 64 + slot * 16;              // kk=1 -> ^0x20
    }
    uint32_t bOff[2];
    {
        int k = lane & 15;
#pragma unroll
        for (int ni = 0; ni < 2; ni++) {
            int nb = wn * 64 + ni * 32 + ((lane >> 4) & 1) * 16;
            bOff[ni] = 4096 + k * 256 + (nb ^ ((k & 7) << 4));  // kk=1 -> +4096
        }
    }

    float acc[2][4][4];
#pragma unroll
    for (int i = 0; i < 2; i++)
#pragma unroll
        for (int j = 0; j < 4; j++)
#pragma unroll
            for (int t = 0; t < 4; t++) acc[i][j][t] = 0.0f;

#define CHUNK(c)                                                               \
    {                                                                          \
        cp_wait<3 - (c)>();                                                    \
        __syncthreads();                                                       \
        const uint32_t buf = sbase + (c) * STAGE_BYTES;                        \
        _Pragma("unroll")                                                      \
        for (int kk = 0; kk < 2; kk++) {                                       \
            uint32_t a[2][4], b[4][2];                                         \
            _Pragma("unroll")                                                  \
            for (int mi = 0; mi < 2; mi++)                                     \
                ldsm4(a[mi], buf + (kk ? (aOff[mi] ^ 0x20) : aOff[mi]));       \
            _Pragma("unroll")                                                  \
            for (int ni = 0; ni < 2; ni++) {                                   \
                uint32_t r[4];                                                 \
                ldsm4t(r, buf + bOff[ni] + (kk ? 4096 : 0));                   \
                b[ni * 2 + 0][0] = r[0]; b[ni * 2 + 0][1] = r[1];              \
                b[ni * 2 + 1][0] = r[2]; b[ni * 2 + 1][1] = r[3];              \
            }                                                                  \
            _Pragma("unroll")                                                  \
            for (int mi = 0; mi < 2; mi++)                                     \
                _Pragma("unroll")                                              \
                for (int ni = 0; ni < 4; ni++)                                 \
                    MMA16816(acc[mi][ni], a[mi], b[ni]);                       \
        }                                                                      \
    }

    CHUNK(0)
    CHUNK(1)
    CHUNK(2)
    CHUNK(3)
#undef CHUNK

    // epilogue: fp32 acc -> fp16 Y
    const int tr = lane >> 2;
    const int tc = (lane & 3) * 2;
#pragma unroll
    for (int mi = 0; mi < 2; mi++) {
#pragma unroll
        for (int ni = 0; ni < 4; ni++) {
            int gr = row0 + wm * 32 + mi * 16 + tr;
            int gc = col0 + wn * 32 + ni * 8 + tc;
            if (gr < M) {
                __half2 v0 = __floats2half2_rn(acc[mi][ni][0], acc[mi][ni][1]);
                *(__half2*)(g_Yh + (size_t)gr * 256 + gc) = v0;
            }
            if (gr + 8 < M) {
                __half2 v1 = __floats2half2_rn(acc[mi][ni][2], acc[mi][ni][3]);
                *(__half2*)(g_Yh + (size_t)(gr + 8) * 256 + gc) = v1;
            }
        }
    }
}

// ---------------------------------------------------------------------------
// Per-edge stage: half-warp split. Lanes 0-15 load 16B each of the src A-half
// (one coalesced 256B request); lanes 16-31 the dst B-half. shfl_xor(16)
// exchanges halves (a+b commutative, both halves compute identical partials);
// reduce over 16 lanes; lane 0 writes. 2-edge unroll for MLP.
// ---------------------------------------------------------------------------
__global__ void edge_kernel(const void* __restrict__ ei,
                            const float* __restrict__ b1,
                            const float* __restrict__ W2,
                            const float* __restrict__ b2,
                            float* __restrict__ out, int E, int M) {
    const int lane = threadIdx.x & 31;
    const int half = lane >> 4;       // 0 = src loader, 1 = dst loader
    const int li = lane & 15;         // hidden-unit group: units [8*li, 8*li+8)

    int gw = (blockIdx.x * blockDim.x + threadIdx.x) >> 5;
    const int nw = (gridDim.x * blockDim.x) >> 5;

    float b1v[8], w2v[8];
    {
        float4 t0 = *(const float4*)(b1 + li * 8);
        float4 t1 = *(const float4*)(b1 + li * 8 + 4);
        b1v[0]=t0.x; b1v[1]=t0.y; b1v[2]=t0.z; b1v[3]=t0.w;
        b1v[4]=t1.x; b1v[5]=t1.y; b1v[6]=t1.z; b1v[7]=t1.w;
        float4 u0 = *(const float4*)(W2 + li * 8);
        float4 u1 = *(const float4*)(W2 + li * 8 + 4);
        w2v[0]=u0.x; w2v[1]=u0.y; w2v[2]=u0.z; w2v[3]=u0.w;
        w2v[4]=u1.x; w2v[5]=u1.y; w2v[6]=u1.z; w2v[7]=u1.w;
    }
    const float b2v = b2[0];
    const int is64 = g_idx_is64;

    const long long* __restrict__ src64 = (const long long*)ei;
    const long long* __restrict__ dst64 = src64 + E;
    const int* __restrict__ src32 = (const int*)ei;
    const int* __restrict__ dst32 = src32 + E;

    const size_t myoff = (size_t)half * 128 + (size_t)li * 8;

    for (int e0 = gw * 2; e0 < E; e0 += nw * 2) {
        int n_e = (e0 + 1 < E) ? 2 : 1;

        int node[2];
#pragma unroll
        for (int u = 0; u < 2; u++) {
            int e = e0 + (u < n_e ? u : 0);
            int s, d;
            if (is64) { s = (int)src64[e]; d = (int)dst64[e]; }
            else      { s = src32[e];      d = dst32[e]; }
            if ((unsigned)s >= (unsigned)M) s = 0;
            if ((unsigned)d >= (unsigned)M) d = 0;
            node[u] = half ? d : s;
        }

        uint4 v[2];
#pragma unroll
        for (int u = 0; u < 2; u++)
            v[u] = *(const uint4*)(g_Yh + (size_t)node[u] * 256 + myoff);

#pragma unroll
        for (int u = 0; u < 2; u++) {
            if (u >= n_e) break;
            uint4 o;
            o.x = __shfl_xor_sync(0xffffffffu, v[u].x, 16);
            o.y = __shfl_xor_sync(0xffffffffu, v[u].y, 16);
            o.z = __shfl_xor_sync(0xffffffffu, v[u].z, 16);
            o.w = __shfl_xor_sync(0xffffffffu, v[u].w, 16);

            float2 a0 = __half22float2(*(__half2*)&v[u].x);
            float2 a1 = __half22float2(*(__half2*)&v[u].y);
            float2 a2 = __half22float2(*(__half2*)&v[u].z);
            float2 a3 = __half22float2(*(__half2*)&v[u].w);
            float2 c0 = __half22float2(*(__half2*)&o.x);
            float2 c1 = __half22float2(*(__half2*)&o.y);
            float2 c2 = __half22float2(*(__half2*)&o.z);
            float2 c3 = __half22float2(*(__half2*)&o.w);

            float p = 0.0f;
            p = fmaf(fmaxf(a0.x + c0.x + b1v[0], 0.f), w2v[0], p);
            p = fmaf(fmaxf(a0.y + c0.y + b1v[1], 0.f), w2v[1], p);
            p = fmaf(fmaxf(a1.x + c1.x + b1v[2], 0.f), w2v[2], p);
            p = fmaf(fmaxf(a1.y + c1.y + b1v[3], 0.f), w2v[3], p);
            p = fmaf(fmaxf(a2.x + c2.x + b1v[4], 0.f), w2v[4], p);
            p = fmaf(fmaxf(a2.y + c2.y + b1v[5], 0.f), w2v[5], p);
            p = fmaf(fmaxf(a3.x + c3.x + b1v[6], 0.f), w2v[6], p);
            p = fmaf(fmaxf(a3.y + c3.y + b1v[7], 0.f), w2v[7], p);

#pragma unroll
            for (int ofs = 8; ofs > 0; ofs >>= 1)
                p += __shfl_xor_sync(0xffffffffu, p, ofs);

            if (lane == 0) out[e0 + u] = p + b2v;
        }
    }
}

// ---------------------------------------------------------------------------
extern "C" void kernel_launch(void* const* d_in, const int* in_sizes, int n_in,
                              void* d_out, int out_size) {
    const float* z  = (const float*)d_in[0];
    const void*  ei = d_in[1];
    const float* W1 = (const float*)d_in[2];
    const float* b1 = (const float*)d_in[3];
    const float* W2 = (const float*)d_in[4];
    const float* b2 = (const float*)d_in[5];
    float*       out = (float*)d_out;

    int M = in_sizes[0] / IN_DIM;
    if (M > NODES_MAX) M = NODES_MAX;
    int E = in_sizes[1] / 2;

    detect_idx_kernel<<<1, 256>>>(ei, E, M);
    prep_z<<<((M * IN_DIM / 4) + 255) / 256, 256>>>(z, M);
    prep_w<<<(IN_DIM * 256 + 255) / 256, 256>>>(W1);

    dim3 ggrid(M_PAD / 64, 2);
    node_gemm_f16<<<ggrid, 256>>>(M);

    edge_kernel<<<1184, 256>>>(ei, b1, W2, b2, out, E, M);
}

// round 10
// speedup vs baseline: 2.7024x; 1.3569x over previous
#include <cuda_runtime.h>
#include <cuda_fp16.h>
#include <cstdint>

#define NODES_MAX 100000
#define M_PAD 100096            // round up to 128
#define IN_DIM 128
#define HIDDEN 128

// Scratch (device globals: no allocations allowed).
__device__ __half g_Yh[(size_t)M_PAD * 256];     // per-node [A|B] features, fp16 (51 MB)
__device__ __half g_Wh[IN_DIM * 256];            // repacked W1 [k][o] fp16
__device__ int g_idx_is64;

// ---------------------------------------------------------------------------
// Detect index width (int64 vs int32 read as int64).
// ---------------------------------------------------------------------------
__global__ void detect_idx_kernel(const void* __restrict__ ei, int E, int M) {
    __shared__ int bad;
    if (threadIdx.x == 0) bad = 0;
    __syncthreads();
    const long long* p = (const long long*)ei;
    int n = E < 512 ? E : 512;
    for (int i = threadIdx.x; i < n; i += blockDim.x) {
        long long v = p[i];
        if (v < 0 || v >= (long long)M) atomicOr(&bad, 1);
    }
    __syncthreads();
    if (threadIdx.x == 0) g_idx_is64 = bad ? 0 : 1;
}

// ---------------------------------------------------------------------------
// Repack W1 (HIDDEN x 2*IN_DIM row-major) into Wh[k][o] fp16.
// ---------------------------------------------------------------------------
__global__ void prep_w(const float* __restrict__ W1) {
    int i = blockIdx.x * blockDim.x + threadIdx.x;
    if (i < IN_DIM * 256) {
        int k = i >> 8, o = i & 255;
        float v = (o < HIDDEN) ? W1[o * (2 * IN_DIM) + k]
                               : W1[(o - HIDDEN) * (2 * IN_DIM) + IN_DIM + k];
        g_Wh[i] = __float2half_rn(v);
    }
}

// ---------------------------------------------------------------------------
// GEMM helpers.
// ---------------------------------------------------------------------------
__device__ __forceinline__ void ldsm4(uint32_t* r, uint32_t addr) {
    asm volatile("ldmatrix.sync.aligned.m8n8.x4.shared.b16 {%0,%1,%2,%3}, [%4];"
                 : "=r"(r[0]), "=r"(r[1]), "=r"(r[2]), "=r"(r[3]) : "r"(addr));
}
__device__ __forceinline__ void ldsm4t(uint32_t* r, uint32_t addr) {
    asm volatile("ldmatrix.sync.aligned.m8n8.x4.trans.shared.b16 {%0,%1,%2,%3}, [%4];"
                 : "=r"(r[0]), "=r"(r[1]), "=r"(r[2]), "=r"(r[3]) : "r"(addr));
}
__device__ __forceinline__ void cp16(uint32_t saddr, const void* gptr) {
    asm volatile("cp.async.cg.shared.global [%0], [%1], 16;" :: "r"(saddr), "l"(gptr));
}
__device__ __forceinline__ void cp_commit() {
    asm volatile("cp.async.commit_group;");
}
template <int N> __device__ __forceinline__ void cp_wait() {
    asm volatile("cp.async.wait_group %0;" :: "n"(N));
}
__device__ __forceinline__ uint4 cvt8(float4 x, float4 y) {
    __half2 h0 = __floats2half2_rn(x.x, x.y);
    __half2 h1 = __floats2half2_rn(x.z, x.w);
    __half2 h2 = __floats2half2_rn(y.x, y.y);
    __half2 h3 = __floats2half2_rn(y.z, y.w);
    uint4 r;
    r.x = *(uint32_t*)&h0; r.y = *(uint32_t*)&h1;
    r.z = *(uint32_t*)&h2; r.w = *(uint32_t*)&h3;
    return r;
}
#define MMA16816(d, a, b)                                                      \
    asm volatile(                                                              \
        "mma.sync.aligned.m16n8k16.row.col.f32.f16.f16.f32 "                   \
        "{%0,%1,%2,%3}, {%4,%5,%6,%7}, {%8,%9}, {%0,%1,%2,%3};"                \
        : "+f"(d[0]), "+f"(d[1]), "+f"(d[2]), "+f"(d[3])                       \
        : "r"(a[0]), "r"(a[1]), "r"(a[2]), "r"(a[3]), "r"(b[0]), "r"(b[1]))

// ---------------------------------------------------------------------------
// Tensor-core GEMM with fused fp32->fp16 A conversion:
//   Yh[M x 256] = cvt(z)[M x 128] @ Wh[128 x 256]
// CTA tile 64x128, 8 warps (2m x 4n of 32x32). K=128 as 4 chunks of 32.
// B: all 4 stages cp.async-prefetched up front (one commit group per stage).
// A: LDG fp32 -> cvt -> STS, pipelined one stage ahead of consumption
//    (STS of stage c+1 happens before the syncthreads that opens chunk c+1).
// Stage layout (12KB): A 64rows x 64B at +0; B 32krows x 256B at +4096.
// Swizzles identical to validated R8 kernel.
// ---------------------------------------------------------------------------
#define STAGE_BYTES 12288

__global__ __launch_bounds__(256, 3) void node_gemm_f16(const float* __restrict__ z, int M) {
    __shared__ __align__(16) unsigned char smem[4 * STAGE_BYTES];

    const int tid = threadIdx.x;
    const int lane = tid & 31;
    const int w = tid >> 5;
    const int wm = w & 1;          // 2 warps along M (32 rows each)
    const int wn = w >> 1;         // 4 warps along N (32 cols each)
    const int row0 = blockIdx.x * 64;
    const int col0 = blockIdx.y * 128;

    const uint32_t sbase = (uint32_t)__cvta_generic_to_shared(&smem[0]);

    // ---- B async store mapping (unchanged from R8) ----
    const int bk = tid >> 3;
    const int bs = tid & 7;
    const uint32_t sB0 = sbase + 4096 + bk * 256 + (((bs) << 4) ^ ((bk & 7) << 4));
    const uint32_t sB1 = sbase + 4096 + bk * 256 + (((bs + 8) << 4) ^ ((bk & 7) << 4));
    const __half* BgBase = g_Wh + (size_t)bk * 256 + col0 + bs * 8;

    // Issue all 4 B stages (one commit group per k-chunk).
#pragma unroll
    for (int c = 0; c < 4; c++) {
        uint32_t st = c * STAGE_BYTES;
        cp16(sB0 + st, BgBase + (size_t)c * 32 * 256);
        cp16(sB1 + st, BgBase + (size_t)c * 32 * 256 + 64);
        cp_commit();
    }

    // ---- A store mapping: row=tid>>2, 16B slot=tid&3 ----
    const int ar = tid >> 2;
    const int as = tid & 3;
    const int aByte = ar * 64 + (((as) ^ ((ar >> 1) & 3)) << 4);
    const int arow = row0 + ar;
    const float* Az = z + (size_t)(arow < M ? arow : 0) * 128 + as * 8;

    // A pipeline: stage c reads fp32 cols [c*32 + as*8, +8).
    float4 rfa, rfb;
    rfa = *(const float4*)(Az);          // chunk 0
    rfb = *(const float4*)(Az + 4);
    *(uint4*)(&smem[0 * STAGE_BYTES + aByte]) = cvt8(rfa, rfb);
    rfa = *(const float4*)(Az + 32);     // chunk 1
    rfb = *(const float4*)(Az + 36);

    // ---- ldmatrix per-thread offsets (within a stage) ----
    uint32_t aOff[2];
#pragma unroll
    for (int mi = 0; mi < 2; mi++) {
        int r = wm * 32 + mi * 16 + (lane & 15);
        int slot = (lane >> 4) ^ ((r >> 1) & 3);
        aOff[mi] = r * 64 + slot * 16;              // kk=1 -> ^0x20
    }
    uint32_t bOff[2];
    {
        int k = lane & 15;
#pragma unroll
        for (int ni = 0; ni < 2; ni++) {
            int nb = wn * 64 + ni * 32 + ((lane >> 4) & 1) * 16;
            bOff[ni] = 4096 + k * 256 + (nb ^ ((k & 7) << 4));  // kk=1 -> +4096
        }
    }

    float acc[2][4][4];
#pragma unroll
    for (int i = 0; i < 2; i++)
#pragma unroll
        for (int j = 0; j < 4; j++)
#pragma unroll
            for (int t = 0; t < 4; t++) acc[i][j][t] = 0.0f;

    // CHUNK(c): wait B stage c, barrier (also makes A STS stage c visible),
    // then STS A stage c+1 / LDG A stage c+2 interleaved with the MMA work.
#define CHUNK(c)                                                               \
    {                                                                          \
        cp_wait<3 - (c)>();                                                    \
        __syncthreads();                                                       \
        if ((c) < 3) {                                                         \
            *(uint4*)(&smem[((c) + 1) * STAGE_BYTES + aByte]) = cvt8(rfa, rfb);\
            if ((c) < 2) {                                                     \
                rfa = *(const float4*)(Az + ((c) + 2) * 32);                   \
                rfb = *(const float4*)(Az + ((c) + 2) * 32 + 4);               \
            }                                                                  \
        }                                                                      \
        const uint32_t buf = sbase + (c) * STAGE_BYTES;                        \
        _Pragma("unroll")                                                      \
        for (int kk = 0; kk < 2; kk++) {                                       \
            uint32_t a[2][4], b[4][2];                                         \
            _Pragma("unroll")                                                  \
            for (int mi = 0; mi < 2; mi++)                                     \
                ldsm4(a[mi], buf + (kk ? (aOff[mi] ^ 0x20) : aOff[mi]));       \
            _Pragma("unroll")                                                  \
            for (int ni = 0; ni < 2; ni++) {                                   \
                uint32_t r[4];                                                 \
                ldsm4t(r, buf + bOff[ni] + (kk ? 4096 : 0));                   \
                b[ni * 2 + 0][0] = r[0]; b[ni * 2 + 0][1] = r[1];              \
                b[ni * 2 + 1][0] = r[2]; b[ni * 2 + 1][1] = r[3];              \
            }                                                                  \
            _Pragma("unroll")                                                  \
            for (int mi = 0; mi < 2; mi++)                                     \
                _Pragma("unroll")                                              \
                for (int ni = 0; ni < 4; ni++)                                 \
                    MMA16816(acc[mi][ni], a[mi], b[ni]);                       \
        }                                                                      \
    }

    CHUNK(0)
    CHUNK(1)
    CHUNK(2)
    CHUNK(3)
#undef CHUNK

    // epilogue: fp32 acc -> fp16 Y
    const int tr = lane >> 2;
    const int tc = (lane & 3) * 2;
#pragma unroll
    for (int mi = 0; mi < 2; mi++) {
#pragma unroll
        for (int ni = 0; ni < 4; ni++) {
            int gr = row0 + wm * 32 + mi * 16 + tr;
            int gc = col0 + wn * 32 + ni * 8 + tc;
            if (gr < M) {
                __half2 v0 = __floats2half2_rn(acc[mi][ni][0], acc[mi][ni][1]);
                *(__half2*)(g_Yh + (size_t)gr * 256 + gc) = v0;
            }
            if (gr + 8 < M) {
                __half2 v1 = __floats2half2_rn(acc[mi][ni][2], acc[mi][ni][3]);
                *(__half2*)(g_Yh + (size_t)(gr + 8) * 256 + gc) = v1;
            }
        }
    }
}

// ---------------------------------------------------------------------------
// Per-edge stage v3: full warp per edge, lane l owns hidden units [4l, 4l+4).
// Per edge: two naturally-coalesced 256B loads (8B/lane), no exchange
// shuffles, 5-level butterfly reduce. 4-edge unroll -> 8 gathers in flight.
// Lane 0 writes 4 outputs as one float4.
// ---------------------------------------------------------------------------
__global__ void edge_kernel(const void* __restrict__ ei,
                            const float* __restrict__ b1,
                            const float* __restrict__ W2,
                            const float* __restrict__ b2,
                            float* __restrict__ out, int E, int M) {
    const int lane = threadIdx.x & 31;
    int gw = (blockIdx.x * blockDim.x + threadIdx.x) >> 5;
    const int nw = (gridDim.x * blockDim.x) >> 5;

    const float4 b1q = *(const float4*)(b1 + lane * 4);
    const float4 w2q = *(const float4*)(W2 + lane * 4);
    const float b2v = b2[0];
    const int is64 = g_idx_is64;

    const long long* __restrict__ src64 = (const long long*)ei;
    const long long* __restrict__ dst64 = src64 + E;
    const int* __restrict__ src32 = (const int*)ei;
    const int* __restrict__ dst32 = src32 + E;

    for (int e0 = gw * 4; e0 < E; e0 += nw * 4) {
        int s[4], d[4];
#pragma unroll
        for (int u = 0; u < 4; u++) {
            int e = e0 + u; if (e >= E) e = E - 1;
            int ss, dd;
            if (is64) { ss = (int)src64[e]; dd = (int)dst64[e]; }
            else      { ss = src32[e];      dd = dst32[e]; }
            if ((unsigned)ss >= (unsigned)M) ss = 0;
            if ((unsigned)dd >= (unsigned)M) dd = 0;
            s[u] = ss; d[u] = dd;
        }

        // issue all 8 gathers before any compute
        uint2 va[4], vb[4];
#pragma unroll
        for (int u = 0; u < 4; u++) {
            va[u] = *(const uint2*)(g_Yh + (size_t)s[u] * 256 + lane * 4);
            vb[u] = *(const uint2*)(g_Yh + (size_t)d[u] * 256 + 128 + lane * 4);
        }

        float p[4];
#pragma unroll
        for (int u = 0; u < 4; u++) {
            float2 a01 = __half22float2(*(__half2*)&va[u].x);
            float2 a23 = __half22float2(*(__half2*)&va[u].y);
            float2 c01 = __half22float2(*(__half2*)&vb[u].x);
            float2 c23 = __half22float2(*(__half2*)&vb[u].y);

            float h0 = fmaxf(a01.x + c01.x + b1q.x, 0.0f);
            float h1 = fmaxf(a01.y + c01.y + b1q.y, 0.0f);
            float h2 = fmaxf(a23.x + c23.x + b1q.z, 0.0f);
            float h3 = fmaxf(a23.y + c23.y + b1q.w, 0.0f);

            float pp = h0 * w2q.x;
            pp = fmaf(h1, w2q.y, pp);
            pp = fmaf(h2, w2q.z, pp);
            pp = fmaf(h3, w2q.w, pp);

#pragma unroll
            for (int ofs = 16; ofs > 0; ofs >>= 1)
                pp += __shfl_xor_sync(0xffffffffu, pp, ofs);
            p[u] = pp;
        }

        if (lane == 0) {
            if (e0 + 3 < E) {
                float4 o4 = make_float4(p[0] + b2v, p[1] + b2v, p[2] + b2v, p[3] + b2v);
                *(float4*)(out + e0) = o4;
            } else {
#pragma unroll
                for (int u = 0; u < 4; u++)
                    if (e0 + u < E) out[e0 + u] = p[u] + b2v;
            }
        }
    }
}

// ---------------------------------------------------------------------------
extern "C" void kernel_launch(void* const* d_in, const int* in_sizes, int n_in,
                              void* d_out, int out_size) {
    const float* z  = (const float*)d_in[0];
    const void*  ei = d_in[1];
    const float* W1 = (const float*)d_in[2];
    const float* b1 = (const float*)d_in[3];
    const float* W2 = (const float*)d_in[4];
    const float* b2 = (const float*)d_in[5];
    float*       out = (float*)d_out;

    int M = in_sizes[0] / IN_DIM;
    if (M > NODES_MAX) M = NODES_MAX;
    int E = in_sizes[1] / 2;

    detect_idx_kernel<<<1, 256>>>(ei, E, M);
    prep_w<<<(IN_DIM * 256 + 255) / 256, 256>>>(W1);

    dim3 ggrid(M_PAD / 64, 2);
    node_gemm_f16<<<ggrid, 256>>>(z, M);

    edge_kernel<<<1184, 256>>>(ei, b1, W2, b2, out, E, M);
}

// round 11
// speedup vs baseline: 3.1027x; 1.1481x over previous
#include <cuda_runtime.h>
#include <cuda_fp16.h>
#include <cstdint>

#define NODES_MAX 100000
#define M_PAD 100096            // round up to 128
#define IN_DIM 128
#define HIDDEN 128

// Scratch (device globals: no allocations allowed).
__device__ __half g_Yh[(size_t)M_PAD * 256];     // per-node [A+b1 | B] features, fp16 (51 MB)
__device__ __half g_Wh[IN_DIM * 256];            // repacked W1 [k][o] fp16
__device__ int g_idx_is64;

// ---------------------------------------------------------------------------
// Detect index width (int64 vs int32 read as int64).
// ---------------------------------------------------------------------------
__global__ void detect_idx_kernel(const void* __restrict__ ei, int E, int M) {
    __shared__ int bad;
    if (threadIdx.x == 0) bad = 0;
    __syncthreads();
    const long long* p = (const long long*)ei;
    int n = E < 512 ? E : 512;
    for (int i = threadIdx.x; i < n; i += blockDim.x) {
        long long v = p[i];
        if (v < 0 || v >= (long long)M) atomicOr(&bad, 1);
    }
    __syncthreads();
    if (threadIdx.x == 0) g_idx_is64 = bad ? 0 : 1;
}

// ---------------------------------------------------------------------------
// Repack W1 (HIDDEN x 2*IN_DIM row-major) into Wh[k][o] fp16.
// ---------------------------------------------------------------------------
__global__ void prep_w(const float* __restrict__ W1) {
    int i = blockIdx.x * blockDim.x + threadIdx.x;
    if (i < IN_DIM * 256) {
        int k = i >> 8, o = i & 255;
        float v = (o < HIDDEN) ? W1[o * (2 * IN_DIM) + k]
                               : W1[(o - HIDDEN) * (2 * IN_DIM) + IN_DIM + k];
        g_Wh[i] = __float2half_rn(v);
    }
}

// ---------------------------------------------------------------------------
// GEMM helpers.
// ---------------------------------------------------------------------------
__device__ __forceinline__ void ldsm4(uint32_t* r, uint32_t addr) {
    asm volatile("ldmatrix.sync.aligned.m8n8.x4.shared.b16 {%0,%1,%2,%3}, [%4];"
                 : "=r"(r[0]), "=r"(r[1]), "=r"(r[2]), "=r"(r[3]) : "r"(addr));
}
__device__ __forceinline__ void ldsm4t(uint32_t* r, uint32_t addr) {
    asm volatile("ldmatrix.sync.aligned.m8n8.x4.trans.shared.b16 {%0,%1,%2,%3}, [%4];"
                 : "=r"(r[0]), "=r"(r[1]), "=r"(r[2]), "=r"(r[3]) : "r"(addr));
}
__device__ __forceinline__ void cp16(uint32_t saddr, const void* gptr) {
    asm volatile("cp.async.cg.shared.global [%0], [%1], 16;" :: "r"(saddr), "l"(gptr));
}
__device__ __forceinline__ void cp_commit() {
    asm volatile("cp.async.commit_group;");
}
template <int N> __device__ __forceinline__ void cp_wait() {
    asm volatile("cp.async.wait_group %0;" :: "n"(N));
}
__device__ __forceinline__ uint4 cvt8(float4 x, float4 y) {
    __half2 h0 = __floats2half2_rn(x.x, x.y);
    __half2 h1 = __floats2half2_rn(x.z, x.w);
    __half2 h2 = __floats2half2_rn(y.x, y.y);
    __half2 h3 = __floats2half2_rn(y.z, y.w);
    uint4 r;
    r.x = *(uint32_t*)&h0; r.y = *(uint32_t*)&h1;
    r.z = *(uint32_t*)&h2; r.w = *(uint32_t*)&h3;
    return r;
}
#define MMA16816(d, a, b)                                                      \
    asm volatile(                                                              \
        "mma.sync.aligned.m16n8k16.row.col.f32.f16.f16.f32 "                   \
        "{%0,%1,%2,%3}, {%4,%5,%6,%7}, {%8,%9}, {%0,%1,%2,%3};"                \
        : "+f"(d[0]), "+f"(d[1]), "+f"(d[2]), "+f"(d[3])                       \
        : "r"(a[0]), "r"(a[1]), "r"(a[2]), "r"(a[3]), "r"(b[0]), "r"(b[1]))

// ---------------------------------------------------------------------------
// Tensor-core GEMM with fused fp32->fp16 A conversion and fused b1 bias:
//   Yh[M x 256] = cvt(z)[M x 128] @ Wh[128 x 256]  (+ b1 on cols 0..127)
// CTA tile 64x128, 8 warps (2m x 4n of 32x32). K=128 as 4 chunks of 32.
// B: all 4 stages cp.async-prefetched up front. A: LDG fp32 -> cvt -> STS,
// pipelined one stage ahead. Swizzles identical to validated R8/R10 kernel.
// ---------------------------------------------------------------------------
#define STAGE_BYTES 12288

__global__ __launch_bounds__(256, 3) void node_gemm_f16(const float* __restrict__ z,
                                                        const float* __restrict__ b1,
                                                        int M) {
    __shared__ __align__(16) unsigned char smem[4 * STAGE_BYTES];

    const int tid = threadIdx.x;
    const int lane = tid & 31;
    const int w = tid >> 5;
    const int wm = w & 1;          // 2 warps along M (32 rows each)
    const int wn = w >> 1;         // 4 warps along N (32 cols each)
    const int row0 = blockIdx.x * 64;
    const int col0 = blockIdx.y * 128;

    const uint32_t sbase = (uint32_t)__cvta_generic_to_shared(&smem[0]);

    // ---- B async store mapping ----
    const int bk = tid >> 3;
    const int bs = tid & 7;
    const uint32_t sB0 = sbase + 4096 + bk * 256 + (((bs) << 4) ^ ((bk & 7) << 4));
    const uint32_t sB1 = sbase + 4096 + bk * 256 + (((bs + 8) << 4) ^ ((bk & 7) << 4));
    const __half* BgBase = g_Wh + (size_t)bk * 256 + col0 + bs * 8;

#pragma unroll
    for (int c = 0; c < 4; c++) {
        uint32_t st = c * STAGE_BYTES;
        cp16(sB0 + st, BgBase + (size_t)c * 32 * 256);
        cp16(sB1 + st, BgBase + (size_t)c * 32 * 256 + 64);
        cp_commit();
    }

    // ---- A store mapping: row=tid>>2, 16B slot=tid&3 ----
    const int ar = tid >> 2;
    const int as = tid & 3;
    const int aByte = ar * 64 + (((as) ^ ((ar >> 1) & 3)) << 4);
    const int arow = row0 + ar;
    const float* Az = z + (size_t)(arow < M ? arow : 0) * 128 + as * 8;

    float4 rfa, rfb;
    rfa = *(const float4*)(Az);          // chunk 0
    rfb = *(const float4*)(Az + 4);
    *(uint4*)(&smem[0 * STAGE_BYTES + aByte]) = cvt8(rfa, rfb);
    rfa = *(const float4*)(Az + 32);     // chunk 1
    rfb = *(const float4*)(Az + 36);

    // ---- ldmatrix per-thread offsets (within a stage) ----
    uint32_t aOff[2];
#pragma unroll
    for (int mi = 0; mi < 2; mi++) {
        int r = wm * 32 + mi * 16 + (lane & 15);
        int slot = (lane >> 4) ^ ((r >> 1) & 3);
        aOff[mi] = r * 64 + slot * 16;              // kk=1 -> ^0x20
    }
    uint32_t bOff[2];
    {
        int k = lane & 15;
#pragma unroll
        for (int ni = 0; ni < 2; ni++) {
            int nb = wn * 64 + ni * 32 + ((lane >> 4) & 1) * 16;
            bOff[ni] = 4096 + k * 256 + (nb ^ ((k & 7) << 4));  // kk=1 -> +4096
        }
    }

    float acc[2][4][4];
#pragma unroll
    for (int i = 0; i < 2; i++)
#pragma unroll
        for (int j = 0; j < 4; j++)
#pragma unroll
            for (int t = 0; t < 4; t++) acc[i][j][t] = 0.0f;

#define CHUNK(c)                                                               \
    {                                                                          \
        cp_wait<3 - (c)>();                                                    \
        __syncthreads();                                                       \
        if ((c) < 3) {                                                         \
            *(uint4*)(&smem[((c) + 1) * STAGE_BYTES + aByte]) = cvt8(rfa, rfb);\
            if ((c) < 2) {                                                     \
                rfa = *(const float4*)(Az + ((c) + 2) * 32);                   \
                rfb = *(const float4*)(Az + ((c) + 2) * 32 + 4);               \
            }                                                                  \
        }                                                                      \
        const uint32_t buf = sbase + (c) * STAGE_BYTES;                        \
        _Pragma("unroll")                                                      \
        for (int kk = 0; kk < 2; kk++) {                                       \
            uint32_t a[2][4], b[4][2];                                         \
            _Pragma("unroll")                                                  \
            for (int mi = 0; mi < 2; mi++)                                     \
                ldsm4(a[mi], buf + (kk ? (aOff[mi] ^ 0x20) : aOff[mi]));       \
            _Pragma("unroll")                                                  \
            for (int ni = 0; ni < 2; ni++) {                                   \
                uint32_t r[4];                                                 \
                ldsm4t(r, buf + bOff[ni] + (kk ? 4096 : 0));                   \
                b[ni * 2 + 0][0] = r[0]; b[ni * 2 + 0][1] = r[1];              \
                b[ni * 2 + 1][0] = r[2]; b[ni * 2 + 1][1] = r[3];              \
            }                                                                  \
            _Pragma("unroll")                                                  \
            for (int mi = 0; mi < 2; mi++)                                     \
                _Pragma("unroll")                                              \
                for (int ni = 0; ni < 4; ni++)                                 \
                    MMA16816(acc[mi][ni], a[mi], b[ni]);                       \
        }                                                                      \
    }

    CHUNK(0)
    CHUNK(1)
    CHUNK(2)
    CHUNK(3)
#undef CHUNK

    // epilogue: fp32 acc (+ b1 on the src half, i.e. blockIdx.y==0) -> fp16 Y
    const int tr = lane >> 2;
    const int tc = (lane & 3) * 2;
    float2 bias[4];
#pragma unroll
    for (int ni = 0; ni < 4; ni++) {
        if (col0 == 0) {
            bias[ni] = *(const float2*)(b1 + wn * 32 + ni * 8 + tc);
        } else {
            bias[ni] = make_float2(0.f, 0.f);
        }
    }
#pragma unroll
    for (int mi = 0; mi < 2; mi++) {
#pragma unroll
        for (int ni = 0; ni < 4; ni++) {
            int gr = row0 + wm * 32 + mi * 16 + tr;
            int gc = col0 + wn * 32 + ni * 8 + tc;
            if (gr < M) {
                __half2 v0 = __floats2half2_rn(acc[mi][ni][0] + bias[ni].x,
                                               acc[mi][ni][1] + bias[ni].y);
                *(__half2*)(g_Yh + (size_t)gr * 256 + gc) = v0;
            }
            if (gr + 8 < M) {
                __half2 v1 = __floats2half2_rn(acc[mi][ni][2] + bias[ni].x,
                                               acc[mi][ni][3] + bias[ni].y);
                *(__half2*)(g_Yh + (size_t)(gr + 8) * 256 + gc) = v1;
            }
        }
    }
}

// ---------------------------------------------------------------------------
// Per-edge stage v4: full warp per edge, lane l owns hidden units [4l, 4l+4).
// Bias pre-folded into Y's src half => h = hmax2(hadd2(a, b), 0) in fp16
// (2 HADD2 + 2 HMAX2), then 4 CVT + 4 FFMA in fp32 for the W2 dot.
// 8-edge unroll -> 16 gathers in flight. Lane 0 writes 2x float4.
// ---------------------------------------------------------------------------
#define EUNROLL 8

__global__ void edge_kernel(const void* __restrict__ ei,
                            const float* __restrict__ W2,
                            const float* __restrict__ b2,
                            float* __restrict__ out, int E, int M) {
    const int lane = threadIdx.x & 31;
    int gw = (blockIdx.x * blockDim.x + threadIdx.x) >> 5;
    const int nw = (gridDim.x * blockDim.x) >> 5;

    const float4 w2q = *(const float4*)(W2 + lane * 4);
    const float b2v = b2[0];
    const int is64 = g_idx_is64;
    const __half2 z2 = __float2half2_rn(0.0f);

    const long long* __restrict__ src64 = (const long long*)ei;
    const long long* __restrict__ dst64 = src64 + E;
    const int* __restrict__ src32 = (const int*)ei;
    const int* __restrict__ dst32 = src32 + E;

    for (int e0 = gw * EUNROLL; e0 < E; e0 += nw * EUNROLL) {
        int s[EUNROLL], d[EUNROLL];
#pragma unroll
        for (int u = 0; u < EUNROLL; u++) {
            int e = e0 + u; if (e >= E) e = E - 1;
            int ss, dd;
            if (is64) { ss = (int)src64[e]; dd = (int)dst64[e]; }
            else      { ss = src32[e];      dd = dst32[e]; }
            if ((unsigned)ss >= (unsigned)M) ss = 0;
            if ((unsigned)dd >= (unsigned)M) dd = 0;
            s[u] = ss; d[u] = dd;
        }

        // issue all gathers before any compute
        uint2 va[EUNROLL], vb[EUNROLL];
#pragma unroll
        for (int u = 0; u < EUNROLL; u++) {
            va[u] = *(const uint2*)(g_Yh + (size_t)s[u] * 256 + lane * 4);
            vb[u] = *(const uint2*)(g_Yh + (size_t)d[u] * 256 + 128 + lane * 4);
        }

        float p[EUNROLL];
#pragma unroll
        for (int u = 0; u < EUNROLL; u++) {
            __half2 h01 = __hmax2(__hadd2(*(__half2*)&va[u].x, *(__half2*)&vb[u].x), z2);
            __half2 h23 = __hmax2(__hadd2(*(__half2*)&va[u].y, *(__half2*)&vb[u].y), z2);
            float2 f01 = __half22float2(h01);
            float2 f23 = __half22float2(h23);

            float pp = f01.x * w2q.x;
            pp = fmaf(f01.y, w2q.y, pp);
            pp = fmaf(f23.x, w2q.z, pp);
            pp = fmaf(f23.y, w2q.w, pp);

#pragma unroll
            for (int ofs = 16; ofs > 0; ofs >>= 1)
                pp += __shfl_xor_sync(0xffffffffu, pp, ofs);
            p[u] = pp;
        }

        if (lane == 0) {
            if (e0 + EUNROLL <= E) {
                float4 o0 = make_float4(p[0] + b2v, p[1] + b2v, p[2] + b2v, p[3] + b2v);
                float4 o1 = make_float4(p[4] + b2v, p[5] + b2v, p[6] + b2v, p[7] + b2v);
                *(float4*)(out + e0) = o0;
                *(float4*)(out + e0 + 4) = o1;
            } else {
#pragma unroll
                for (int u = 0; u < EUNROLL; u++)
                    if (e0 + u < E) out[e0 + u] = p[u] + b2v;
            }
        }
    }
}

// ---------------------------------------------------------------------------
extern "C" void kernel_launch(void* const* d_in, const int* in_sizes, int n_in,
                              void* d_out, int out_size) {
    const float* z  = (const float*)d_in[0];
    const void*  ei = d_in[1];
    const float* W1 = (const float*)d_in[2];
    const float* b1 = (const float*)d_in[3];
    const float* W2 = (const float*)d_in[4];
    const float* b2 = (const float*)d_in[5];
    float*       out = (float*)d_out;

    int M = in_sizes[0] / IN_DIM;
    if (M > NODES_MAX) M = NODES_MAX;
    int E = in_sizes[1] / 2;

    detect_idx_kernel<<<1, 256>>>(ei, E, M);
    prep_w<<<(IN_DIM * 256 + 255) / 256, 256>>>(W1);

    dim3 ggrid(M_PAD / 64, 2);
    node_gemm_f16<<<ggrid, 256>>>(z, b1, M);

    edge_kernel<<<1184, 256>>>(ei, W2, b2, out, E, M);
}

// round 13
// speedup vs baseline: 3.2873x; 1.0595x over previous
#include <cuda_runtime.h>
#include <cuda_fp16.h>
#include <cstdint>

#define NODES_MAX 100000
#define M_PAD 100096            // round up to 128
#define IN_DIM 128
#define HIDDEN 128

// Scratch (device globals: no allocations allowed).
__device__ __half g_Yh[(size_t)M_PAD * 256];     // per-node [A+b1 | B] features, fp16 (51 MB)
__device__ __half g_Wh[IN_DIM * 256];            // repacked W1 [k][o] fp16
__device__ int g_idx_is64;

// ---------------------------------------------------------------------------
// Detect index width (int64 vs int32 read as int64).
// ---------------------------------------------------------------------------
__global__ void detect_idx_kernel(const void* __restrict__ ei, int E, int M) {
    __shared__ int bad;
    if (threadIdx.x == 0) bad = 0;
    __syncthreads();
    const long long* p = (const long long*)ei;
    int n = E < 512 ? E : 512;
    for (int i = threadIdx.x; i < n; i += blockDim.x) {
        long long v = p[i];
        if (v < 0 || v >= (long long)M) atomicOr(&bad, 1);
    }
    __syncthreads();
    if (threadIdx.x == 0) g_idx_is64 = bad ? 0 : 1;
}

// ---------------------------------------------------------------------------
// Repack W1 (HIDDEN x 2*IN_DIM row-major) into Wh[k][o] fp16.
// ---------------------------------------------------------------------------
__global__ void prep_w(const float* __restrict__ W1) {
    int i = blockIdx.x * blockDim.x + threadIdx.x;
    if (i < IN_DIM * 256) {
        int k = i >> 8, o = i & 255;
        float v = (o < HIDDEN) ? W1[o * (2 * IN_DIM) + k]
                               : W1[(o - HIDDEN) * (2 * IN_DIM) + IN_DIM + k];
        g_Wh[i] = __float2half_rn(v);
    }
}

// ---------------------------------------------------------------------------
// GEMM helpers.
// ---------------------------------------------------------------------------
__device__ __forceinline__ void ldsm4(uint32_t* r, uint32_t addr) {
    asm volatile("ldmatrix.sync.aligned.m8n8.x4.shared.b16 {%0,%1,%2,%3}, [%4];"
                 : "=r"(r[0]), "=r"(r[1]), "=r"(r[2]), "=r"(r[3]) : "r"(addr));
}
__device__ __forceinline__ void ldsm4t(uint32_t* r, uint32_t addr) {
    asm volatile("ldmatrix.sync.aligned.m8n8.x4.trans.shared.b16 {%0,%1,%2,%3}, [%4];"
                 : "=r"(r[0]), "=r"(r[1]), "=r"(r[2]), "=r"(r[3]) : "r"(addr));
}
__device__ __forceinline__ void cp16(uint32_t saddr, const void* gptr) {
    asm volatile("cp.async.cg.shared.global [%0], [%1], 16;" :: "r"(saddr), "l"(gptr));
}
__device__ __forceinline__ void cp_commit() {
    asm volatile("cp.async.commit_group;");
}
template <int N> __device__ __forceinline__ void cp_wait() {
    asm volatile("cp.async.wait_group %0;" :: "n"(N));
}
__device__ __forceinline__ uint4 cvt8(float4 x, float4 y) {
    __half2 h0 = __floats2half2_rn(x.x, x.y);
    __half2 h1 = __floats2half2_rn(x.z, x.w);
    __half2 h2 = __floats2half2_rn(y.x, y.y);
    __half2 h3 = __floats2half2_rn(y.z, y.w);
    uint4 r;
    r.x = *(uint32_t*)&h0; r.y = *(uint32_t*)&h1;
    r.z = *(uint32_t*)&h2; r.w = *(uint32_t*)&h3;
    return r;
}
#define MMA16816(d, a, b)                                                      \
    asm volatile(                                                              \
        "mma.sync.aligned.m16n8k16.row.col.f32.f16.f16.f32 "                   \
        "{%0,%1,%2,%3}, {%4,%5,%6,%7}, {%8,%9}, {%0,%1,%2,%3};"                \
        : "+f"(d[0]), "+f"(d[1]), "+f"(d[2]), "+f"(d[3])                       \
        : "r"(a[0]), "r"(a[1]), "r"(a[2]), "r"(a[3]), "r"(b[0]), "r"(b[1]))

// ---------------------------------------------------------------------------
// Tensor-core GEMM with fused fp32->fp16 A conversion and fused b1 bias:
//   Yh[M x 256] = cvt(z)[M x 128] @ Wh[128 x 256]  (+ b1 on cols 0..127)
// Identical to validated R11 kernel.
// ---------------------------------------------------------------------------
#define STAGE_BYTES 12288

__global__ __launch_bounds__(256, 3) void node_gemm_f16(const float* __restrict__ z,
                                                        const float* __restrict__ b1,
                                                        int M) {
    __shared__ __align__(16) unsigned char smem[4 * STAGE_BYTES];

    const int tid = threadIdx.x;
    const int lane = tid & 31;
    const int w = tid >> 5;
    const int wm = w & 1;          // 2 warps along M (32 rows each)
    const int wn = w >> 1;         // 4 warps along N (32 cols each)
    const int row0 = blockIdx.x * 64;
    const int col0 = blockIdx.y * 128;

    const uint32_t sbase = (uint32_t)__cvta_generic_to_shared(&smem[0]);

    // ---- B async store mapping ----
    const int bk = tid >> 3;
    const int bs = tid & 7;
    const uint32_t sB0 = sbase + 4096 + bk * 256 + (((bs) << 4) ^ ((bk & 7) << 4));
    const uint32_t sB1 = sbase + 4096 + bk * 256 + (((bs + 8) << 4) ^ ((bk & 7) << 4));
    const __half* BgBase = g_Wh + (size_t)bk * 256 + col0 + bs * 8;

#pragma unroll
    for (int c = 0; c < 4; c++) {
        uint32_t st = c * STAGE_BYTES;
        cp16(sB0 + st, BgBase + (size_t)c * 32 * 256);
        cp16(sB1 + st, BgBase + (size_t)c * 32 * 256 + 64);
        cp_commit();
    }

    // ---- A store mapping: row=tid>>2, 16B slot=tid&3 ----
    const int ar = tid >> 2;
    const int as = tid & 3;
    const int aByte = ar * 64 + (((as) ^ ((ar >> 1) & 3)) << 4);
    const int arow = row0 + ar;
    const float* Az = z + (size_t)(arow < M ? arow : 0) * 128 + as * 8;

    float4 rfa, rfb;
    rfa = *(const float4*)(Az);          // chunk 0
    rfb = *(const float4*)(Az + 4);
    *(uint4*)(&smem[0 * STAGE_BYTES + aByte]) = cvt8(rfa, rfb);
    rfa = *(const float4*)(Az + 32);     // chunk 1
    rfb = *(const float4*)(Az + 36);

    // ---- ldmatrix per-thread offsets (within a stage) ----
    uint32_t aOff[2];
#pragma unroll
    for (int mi = 0; mi < 2; mi++) {
        int r = wm * 32 + mi * 16 + (lane & 15);
        int slot = (lane >> 4) ^ ((r >> 1) & 3);
        aOff[mi] = r * 64 + slot * 16;              // kk=1 -> ^0x20
    }
    uint32_t bOff[2];
    {
        int k = lane & 15;
#pragma unroll
        for (int ni = 0; ni < 2; ni++) {
            int nb = wn * 64 + ni * 32 + ((lane >> 4) & 1) * 16;
            bOff[ni] = 4096 + k * 256 + (nb ^ ((k & 7) << 4));  // kk=1 -> +4096
        }
    }

    float acc[2][4][4];
#pragma unroll
    for (int i = 0; i < 2; i++)
#pragma unroll
        for (int j = 0; j < 4; j++)
#pragma unroll
            for (int t = 0; t < 4; t++) acc[i][j][t] = 0.0f;

#define CHUNK(c)                                                               \
    {                                                                          \
        cp_wait<3 - (c)>();                                                    \
        __syncthreads();                                                       \
        if ((c) < 3) {                                                         \
            *(uint4*)(&smem[((c) + 1) * STAGE_BYTES + aByte]) = cvt8(rfa, rfb);\
            if ((c) < 2) {                                                     \
                rfa = *(const float4*)(Az + ((c) + 2) * 32);                   \
                rfb = *(const float4*)(Az + ((c) + 2) * 32 + 4);               \
            }                                                                  \
        }                                                                      \
        const uint32_t buf = sbase + (c) * STAGE_BYTES;                        \
        _Pragma("unroll")                                                      \
        for (int kk = 0; kk < 2; kk++) {                                       \
            uint32_t a[2][4], b[4][2];                                         \
            _Pragma("unroll")                                                  \
            for (int mi = 0; mi < 2; mi++)                                     \
                ldsm4(a[mi], buf + (kk ? (aOff[mi] ^ 0x20) : aOff[mi]));       \
            _Pragma("unroll")                                                  \
            for (int ni = 0; ni < 2; ni++) {                                   \
                uint32_t r[4];                                                 \
                ldsm4t(r, buf + bOff[ni] + (kk ? 4096 : 0));                   \
                b[ni * 2 + 0][0] = r[0]; b[ni * 2 + 0][1] = r[1];              \
                b[ni * 2 + 1][0] = r[2]; b[ni * 2 + 1][1] = r[3];              \
            }                                                                  \
            _Pragma("unroll")                                                  \
            for (int mi = 0; mi < 2; mi++)                                     \
                _Pragma("unroll")                                              \
                for (int ni = 0; ni < 4; ni++)                                 \
                    MMA16816(acc[mi][ni], a[mi], b[ni]);                       \
        }                                                                      \
    }

    CHUNK(0)
    CHUNK(1)
    CHUNK(2)
    CHUNK(3)
#undef CHUNK

    // epilogue: fp32 acc (+ b1 on the src half, i.e. blockIdx.y==0) -> fp16 Y
    const int tr = lane >> 2;
    const int tc = (lane & 3) * 2;
    float2 bias[4];
#pragma unroll
    for (int ni = 0; ni < 4; ni++) {
        if (col0 == 0) {
            bias[ni] = *(const float2*)(b1 + wn * 32 + ni * 8 + tc);
        } else {
            bias[ni] = make_float2(0.f, 0.f);
        }
    }
#pragma unroll
    for (int mi = 0; mi < 2; mi++) {
#pragma unroll
        for (int ni = 0; ni < 4; ni++) {
            int gr = row0 + wm * 32 + mi * 16 + tr;
            int gc = col0 + wn * 32 + ni * 8 + tc;
            if (gr < M) {
                __half2 v0 = __floats2half2_rn(acc[mi][ni][0] + bias[ni].x,
                                               acc[mi][ni][1] + bias[ni].y);
                *(__half2*)(g_Yh + (size_t)gr * 256 + gc) = v0;
            }
            if (gr + 8 < M) {
                __half2 v1 = __floats2half2_rn(acc[mi][ni][2] + bias[ni].x,
                                               acc[mi][ni][3] + bias[ni].y);
                *(__half2*)(g_Yh + (size_t)(gr + 8) * 256 + gc) = v1;
            }
        }
    }
}

// ---------------------------------------------------------------------------
// Per-edge stage v5: 8 lanes per edge (4 edges per warp per group).
// Lane oi (0..7) of octet q owns hidden units [16*oi, 16*oi+16): two uint4
// loads of the src half and two of the dst half. h = hmax2(hadd2(a,b), 0);
// fp32 CVT+FFMA dot with the lane's 16 W2 weights; 3-level butterfly reduce
// over the octet; lane oi==0 stores. 2 groups unrolled -> 8 edges/warp-iter,
// 8 LDG.128 in flight per lane. b2 folded as pp0 = b2/8 (exact).
// ---------------------------------------------------------------------------
__global__ void edge_kernel(const void* __restrict__ ei,
                            const float* __restrict__ W2,
                            const float* __restrict__ b2,
                            float* __restrict__ out, int E, int M) {
    const int lane = threadIdx.x & 31;
    const int octet = lane >> 3;      // which edge of the 4 in the warp
    const int oi = lane & 7;          // unit group within the edge

    int gw = (blockIdx.x * blockDim.x + threadIdx.x) >> 5;
    const int nw = (gridDim.x * blockDim.x) >> 5;

    // Per-lane W2 slice: units [16*oi, 16*oi+16).
    float w2v[16];
#pragma unroll
    for (int j = 0; j < 4; j++) {
        float4 t = *(const float4*)(W2 + oi * 16 + j * 4);
        w2v[j * 4 + 0] = t.x; w2v[j * 4 + 1] = t.y;
        w2v[j * 4 + 2] = t.z; w2v[j * 4 + 3] = t.w;
    }
    const float pp0 = b2[0] * 0.125f;   // b2 distributed over 8 lanes (exact /8)
    const int is64 = g_idx_is64;
    const __half2 z2 = __float2half2_rn(0.0f);

    const long long* __restrict__ src64 = (const long long*)ei;
    const long long* __restrict__ dst64 = src64 + E;
    const int* __restrict__ src32 = (const int*)ei;
    const int* __restrict__ dst32 = src32 + E;

    for (int e0 = gw * 8; e0 < E; e0 += nw * 8) {
        // group g handles edge e0 + g*4 + octet
        int s[2], d[2], ee[2];
#pragma unroll
        for (int g = 0; g < 2; g++) {
            int e = e0 + g * 4 + octet;
            ee[g] = e;
            if (e >= E) e = E - 1;
            int ss, dd;
            if (is64) { ss = (int)src64[e]; dd = (int)dst64[e]; }
            else      { ss = src32[e];      dd = dst32[e]; }
            if ((unsigned)ss >= (unsigned)M) ss = 0;
            if ((unsigned)dd >= (unsigned)M) dd = 0;
            s[g] = ss; d[g] = dd;
        }

        // Issue all 8 gathers before any compute.
        uint4 va[2][2], vb[2][2];
#pragma unroll
        for (int g = 0; g < 2; g++) {
            const __half* ps = g_Yh + (size_t)s[g] * 256 + oi * 16;
            const __half* pd = g_Yh + (size_t)d[g] * 256 + 128 + oi * 16;
            va[g][0] = *(const uint4*)(ps);
            va[g][1] = *(const uint4*)(ps + 8);
            vb[g][0] = *(const uint4*)(pd);
            vb[g][1] = *(const uint4*)(pd + 8);
        }

#pragma unroll
        for (int g = 0; g < 2; g++) {
            float pp = pp0;
            const uint32_t* ua = (const uint32_t*)&va[g][0];
            const uint32_t* ub = (const uint32_t*)&vb[g][0];
#pragma unroll
            for (int j = 0; j < 8; j++) {
                __half2 h = __hmax2(__hadd2(*(const __half2*)&ua[j],
                                            *(const __half2*)&ub[j]), z2);
                float2 f = __half22float2(h);
                pp = fmaf(f.x, w2v[2 * j], pp);
                pp = fmaf(f.y, w2v[2 * j + 1], pp);
            }
            // butterfly over the octet (offsets 4,2,1 stay within 8 lanes)
            pp += __shfl_xor_sync(0xffffffffu, pp, 4);
            pp += __shfl_xor_sync(0xffffffffu, pp, 2);
            pp += __shfl_xor_sync(0xffffffffu, pp, 1);

            if (oi == 0 && ee[g] < E) out[ee[g]] = pp;
        }
    }
}

// ---------------------------------------------------------------------------
extern "C" void kernel_launch(void* const* d_in, const int* in_sizes, int n_in,
                              void* d_out, int out_size) {
    const float* z  = (const float*)d_in[0];
    const void*  ei = d_in[1];
    const float* W1 = (const float*)d_in[2];
    const float* b1 = (const float*)d_in[3];
    const float* W2 = (const float*)d_in[4];
    const float* b2 = (const float*)d_in[5];
    float*       out = (float*)d_out;

    int M = in_sizes[0] / IN_DIM;
    if (M > NODES_MAX) M = NODES_MAX;
    int E = in_sizes[1] / 2;

    detect_idx_kernel<<<1, 256>>>(ei, E, M);
    prep_w<<<(IN_DIM * 256 + 255) / 256, 256>>>(W1);

    dim3 ggrid(M_PAD / 64, 2);
    node_gemm_f16<<<ggrid, 256>>>(z, b1, M);

    edge_kernel<<<1184, 256>>>(ei, W2, b2, out, E, M);
}

// round 14
// speedup vs baseline: 3.4413x; 1.0468x over previous
#include <cuda_runtime.h>
#include <cuda_fp16.h>
#include <cstdint>

#define NODES_MAX 100000
#define M_PAD 100096            // round up to 128
#define IN_DIM 128
#define HIDDEN 128

// Scratch (device globals: no allocations allowed).
__device__ __half g_Yh[(size_t)M_PAD * 256];     // per-node [A+b1 | B] features, fp16 (51 MB)
__device__ __half g_Wh[IN_DIM * 256];            // repacked W1 [k][o] fp16
__device__ int g_idx_is64;

// ---------------------------------------------------------------------------
// Fused prep: blocks [0,128) repack W1 -> Wh fp16; block 128 detects index
// width (int64 vs int32 read as int64).
// ---------------------------------------------------------------------------
__global__ void prep_kernel(const float* __restrict__ W1,
                            const void* __restrict__ ei, int E, int M) {
    if (blockIdx.x == gridDim.x - 1) {
        __shared__ int bad;
        if (threadIdx.x == 0) bad = 0;
        __syncthreads();
        const long long* p = (const long long*)ei;
        int n = E < 512 ? E : 512;
        for (int i = threadIdx.x; i < n; i += blockDim.x) {
            long long v = p[i];
            if (v < 0 || v >= (long long)M) atomicOr(&bad, 1);
        }
        __syncthreads();
        if (threadIdx.x == 0) g_idx_is64 = bad ? 0 : 1;
        return;
    }
    int i = blockIdx.x * blockDim.x + threadIdx.x;
    if (i < IN_DIM * 256) {
        int k = i >> 8, o = i & 255;
        float v = (o < HIDDEN) ? W1[o * (2 * IN_DIM) + k]
                               : W1[(o - HIDDEN) * (2 * IN_DIM) + IN_DIM + k];
        g_Wh[i] = __float2half_rn(v);
    }
}

// ---------------------------------------------------------------------------
// GEMM helpers.
// ---------------------------------------------------------------------------
__device__ __forceinline__ void ldsm4(uint32_t* r, uint32_t addr) {
    asm volatile("ldmatrix.sync.aligned.m8n8.x4.shared.b16 {%0,%1,%2,%3}, [%4];"
                 : "=r"(r[0]), "=r"(r[1]), "=r"(r[2]), "=r"(r[3]) : "r"(addr));
}
__device__ __forceinline__ void ldsm4t(uint32_t* r, uint32_t addr) {
    asm volatile("ldmatrix.sync.aligned.m8n8.x4.trans.shared.b16 {%0,%1,%2,%3}, [%4];"
                 : "=r"(r[0]), "=r"(r[1]), "=r"(r[2]), "=r"(r[3]) : "r"(addr));
}
__device__ __forceinline__ void cp16(uint32_t saddr, const void* gptr) {
    asm volatile("cp.async.cg.shared.global [%0], [%1], 16;" :: "r"(saddr), "l"(gptr));
}
__device__ __forceinline__ void cp_commit() {
    asm volatile("cp.async.commit_group;");
}
template <int N> __device__ __forceinline__ void cp_wait() {
    asm volatile("cp.async.wait_group %0;" :: "n"(N));
}
__device__ __forceinline__ uint4 cvt8(float4 x, float4 y) {
    __half2 h0 = __floats2half2_rn(x.x, x.y);
    __half2 h1 = __floats2half2_rn(x.z, x.w);
    __half2 h2 = __floats2half2_rn(y.x, y.y);
    __half2 h3 = __floats2half2_rn(y.z, y.w);
    uint4 r;
    r.x = *(uint32_t*)&h0; r.y = *(uint32_t*)&h1;
    r.z = *(uint32_t*)&h2; r.w = *(uint32_t*)&h3;
    return r;
}
#define MMA16816(d, a, b)                                                      \
    asm volatile(                                                              \
        "mma.sync.aligned.m16n8k16.row.col.f32.f16.f16.f32 "                   \
        "{%0,%1,%2,%3}, {%4,%5,%6,%7}, {%8,%9}, {%0,%1,%2,%3};"                \
        : "+f"(d[0]), "+f"(d[1]), "+f"(d[2]), "+f"(d[3])                       \
        : "r"(a[0]), "r"(a[1]), "r"(a[2]), "r"(a[3]), "r"(b[0]), "r"(b[1]))

// ---------------------------------------------------------------------------
// Tensor-core GEMM with fused fp32->fp16 A conversion and fused b1 bias:
//   Yh[M x 256] = cvt(z)[M x 128] @ Wh[128 x 256]  (+ b1 on cols 0..127)
// Identical to validated R11/R13 kernel.
// ---------------------------------------------------------------------------
#define STAGE_BYTES 12288

__global__ __launch_bounds__(256, 3) void node_gemm_f16(const float* __restrict__ z,
                                                        const float* __restrict__ b1,
                                                        int M) {
    __shared__ __align__(16) unsigned char smem[4 * STAGE_BYTES];

    const int tid = threadIdx.x;
    const int lane = tid & 31;
    const int w = tid >> 5;
    const int wm = w & 1;          // 2 warps along M (32 rows each)
    const int wn = w >> 1;         // 4 warps along N (32 cols each)
    const int row0 = blockIdx.x * 64;
    const int col0 = blockIdx.y * 128;

    const uint32_t sbase = (uint32_t)__cvta_generic_to_shared(&smem[0]);

    // ---- B async store mapping ----
    const int bk = tid >> 3;
    const int bs = tid & 7;
    const uint32_t sB0 = sbase + 4096 + bk * 256 + (((bs) << 4) ^ ((bk & 7) << 4));
    const uint32_t sB1 = sbase + 4096 + bk * 256 + (((bs + 8) << 4) ^ ((bk & 7) << 4));
    const __half* BgBase = g_Wh + (size_t)bk * 256 + col0 + bs * 8;

#pragma unroll
    for (int c = 0; c < 4; c++) {
        uint32_t st = c * STAGE_BYTES;
        cp16(sB0 + st, BgBase + (size_t)c * 32 * 256);
        cp16(sB1 + st, BgBase + (size_t)c * 32 * 256 + 64);
        cp_commit();
    }

    // ---- A store mapping: row=tid>>2, 16B slot=tid&3 ----
    const int ar = tid >> 2;
    const int as = tid & 3;
    const int aByte = ar * 64 + (((as) ^ ((ar >> 1) & 3)) << 4);
    const int arow = row0 + ar;
    const float* Az = z + (size_t)(arow < M ? arow : 0) * 128 + as * 8;

    float4 rfa, rfb;
    rfa = *(const float4*)(Az);          // chunk 0
    rfb = *(const float4*)(Az + 4);
    *(uint4*)(&smem[0 * STAGE_BYTES + aByte]) = cvt8(rfa, rfb);
    rfa = *(const float4*)(Az + 32);     // chunk 1
    rfb = *(const float4*)(Az + 36);

    // ---- ldmatrix per-thread offsets (within a stage) ----
    uint32_t aOff[2];
#pragma unroll
    for (int mi = 0; mi < 2; mi++) {
        int r = wm * 32 + mi * 16 + (lane & 15);
        int slot = (lane >> 4) ^ ((r >> 1) & 3);
        aOff[mi] = r * 64 + slot * 16;              // kk=1 -> ^0x20
    }
    uint32_t bOff[2];
    {
        int k = lane & 15;
#pragma unroll
        for (int ni = 0; ni < 2; ni++) {
            int nb = wn * 64 + ni * 32 + ((lane >> 4) & 1) * 16;
            bOff[ni] = 4096 + k * 256 + (nb ^ ((k & 7) << 4));  // kk=1 -> +4096
        }
    }

    float acc[2][4][4];
#pragma unroll
    for (int i = 0; i < 2; i++)
#pragma unroll
        for (int j = 0; j < 4; j++)
#pragma unroll
            for (int t = 0; t < 4; t++) acc[i][j][t] = 0.0f;

#define CHUNK(c)                                                               \
    {                                                                          \
        cp_wait<3 - (c)>();                                                    \
        __syncthreads();                                                       \
        if ((c) < 3) {                                                         \
            *(uint4*)(&smem[((c) + 1) * STAGE_BYTES + aByte]) = cvt8(rfa, rfb);\
            if ((c) < 2) {                                                     \
                rfa = *(const float4*)(Az + ((c) + 2) * 32);                   \
                rfb = *(const float4*)(Az + ((c) + 2) * 32 + 4);               \
            }                                                                  \
        }                                                                      \
        const uint32_t buf = sbase + (c) * STAGE_BYTES;                        \
        _Pragma("unroll")                                                      \
        for (int kk = 0; kk < 2; kk++) {                                       \
            uint32_t a[2][4], b[4][2];                                         \
            _Pragma("unroll")                                                  \
            for (int mi = 0; mi < 2; mi++)                                     \
                ldsm4(a[mi], buf + (kk ? (aOff[mi] ^ 0x20) : aOff[mi]));       \
            _Pragma("unroll")                                                  \
            for (int ni = 0; ni < 2; ni++) {                                   \
                uint32_t r[4];                                                 \
                ldsm4t(r, buf + bOff[ni] + (kk ? 4096 : 0));                   \
                b[ni * 2 + 0][0] = r[0]; b[ni * 2 + 0][1] = r[1];              \
                b[ni * 2 + 1][0] = r[2]; b[ni * 2 + 1][1] = r[3];              \
            }                                                                  \
            _Pragma("unroll")                                                  \
            for (int mi = 0; mi < 2; mi++)                                     \
                _Pragma("unroll")                                              \
                for (int ni = 0; ni < 4; ni++)                                 \
                    MMA16816(acc[mi][ni], a[mi], b[ni]);                       \
        }                                                                      \
    }

    CHUNK(0)
    CHUNK(1)
    CHUNK(2)
    CHUNK(3)
#undef CHUNK

    // epilogue: fp32 acc (+ b1 on the src half, i.e. blockIdx.y==0) -> fp16 Y
    const int tr = lane >> 2;
    const int tc = (lane & 3) * 2;
    float2 bias[4];
#pragma unroll
    for (int ni = 0; ni < 4; ni++) {
        if (col0 == 0) {
            bias[ni] = *(const float2*)(b1 + wn * 32 + ni * 8 + tc);
        } else {
            bias[ni] = make_float2(0.f, 0.f);
        }
    }
#pragma unroll
    for (int mi = 0; mi < 2; mi++) {
#pragma unroll
        for (int ni = 0; ni < 4; ni++) {
            int gr = row0 + wm * 32 + mi * 16 + tr;
            int gc = col0 + wn * 32 + ni * 8 + tc;
            if (gr < M) {
                __half2 v0 = __floats2half2_rn(acc[mi][ni][0] + bias[ni].x,
                                               acc[mi][ni][1] + bias[ni].y);
                *(__half2*)(g_Yh + (size_t)gr * 256 + gc) = v0;
            }
            if (gr + 8 < M) {
                __half2 v1 = __floats2half2_rn(acc[mi][ni][2] + bias[ni].x,
                                               acc[mi][ni][3] + bias[ni].y);
                *(__half2*)(g_Yh + (size_t)(gr + 8) * 256 + gc) = v1;
            }
        }
    }
}

// ---------------------------------------------------------------------------
// Per-edge stage v6: 8 lanes per edge (4 edges/warp/group, 2 groups).
// Same structure as validated v5, but W2 held as 8x half2 registers
// (converted to fp32 at use; dot math stays fp32) to cut regs 56 -> ~48,
// and __launch_bounds__(256,5) to hold 40 resident warps/SM.
// ---------------------------------------------------------------------------
__global__ __launch_bounds__(256, 5) void edge_kernel(
        const void* __restrict__ ei,
        const float* __restrict__ W2,
        const float* __restrict__ b2,
        float* __restrict__ out, int E, int M) {
    const int lane = threadIdx.x & 31;
    const int octet = lane >> 3;      // which edge of the 4 in the warp
    const int oi = lane & 7;          // unit group within the edge

    int gw = (blockIdx.x * blockDim.x + threadIdx.x) >> 5;
    const int nw = (gridDim.x * blockDim.x) >> 5;

    // Per-lane W2 slice: units [16*oi, 16*oi+16), packed as 8 half2.
    __half2 w2h[8];
#pragma unroll
    for (int j = 0; j < 4; j++) {
        float4 t = *(const float4*)(W2 + oi * 16 + j * 4);
        w2h[j * 2 + 0] = __floats2half2_rn(t.x, t.y);
        w2h[j * 2 + 1] = __floats2half2_rn(t.z, t.w);
    }
    const float pp0 = b2[0] * 0.125f;   // b2 distributed over 8 lanes (exact /8)
    const int is64 = g_idx_is64;
    const __half2 z2 = __float2half2_rn(0.0f);

    const long long* __restrict__ src64 = (const long long*)ei;
    const long long* __restrict__ dst64 = src64 + E;
    const int* __restrict__ src32 = (const int*)ei;
    const int* __restrict__ dst32 = src32 + E;

    for (int e0 = gw * 8; e0 < E; e0 += nw * 8) {
        // group g handles edge e0 + g*4 + octet
        int s[2], d[2], ee[2];
#pragma unroll
        for (int g = 0; g < 2; g++) {
            int e = e0 + g * 4 + octet;
            ee[g] = e;
            if (e >= E) e = E - 1;
            int ss, dd;
            if (is64) { ss = (int)src64[e]; dd = (int)dst64[e]; }
            else      { ss = src32[e];      dd = dst32[e]; }
            if ((unsigned)ss >= (unsigned)M) ss = 0;
            if ((unsigned)dd >= (unsigned)M) dd = 0;
            s[g] = ss; d[g] = dd;
        }

        // Issue all 8 gathers before any compute.
        uint4 va[2][2], vb[2][2];
#pragma unroll
        for (int g = 0; g < 2; g++) {
            const __half* ps = g_Yh + (size_t)s[g] * 256 + oi * 16;
            const __half* pd = g_Yh + (size_t)d[g] * 256 + 128 + oi * 16;
            va[g][0] = *(const uint4*)(ps);
            va[g][1] = *(const uint4*)(ps + 8);
            vb[g][0] = *(const uint4*)(pd);
            vb[g][1] = *(const uint4*)(pd + 8);
        }

#pragma unroll
        for (int g = 0; g < 2; g++) {
            float pp = pp0;
            const uint32_t* ua = (const uint32_t*)&va[g][0];
            const uint32_t* ub = (const uint32_t*)&vb[g][0];
#pragma unroll
            for (int j = 0; j < 8; j++) {
                __half2 h = __hmax2(__hadd2(*(const __half2*)&ua[j],
                                            *(const __half2*)&ub[j]), z2);
                float2 f = __half22float2(h);
                float2 wf = __half22float2(w2h[j]);
                pp = fmaf(f.x, wf.x, pp);
                pp = fmaf(f.y, wf.y, pp);
            }
            // butterfly over the octet (offsets 4,2,1 stay within 8 lanes)
            pp += __shfl_xor_sync(0xffffffffu, pp, 4);
            pp += __shfl_xor_sync(0xffffffffu, pp, 2);
            pp += __shfl_xor_sync(0xffffffffu, pp, 1);

            if (oi == 0 && ee[g] < E) out[ee[g]] = pp;
        }
    }
}

// ---------------------------------------------------------------------------
extern "C" void kernel_launch(void* const* d_in, const int* in_sizes, int n_in,
                              void* d_out, int out_size) {
    const float* z  = (const float*)d_in[0];
    const void*  ei = d_in[1];
    const float* W1 = (const float*)d_in[2];
    const float* b1 = (const float*)d_in[3];
    const float* W2 = (const float*)d_in[4];
    const float* b2 = (const float*)d_in[5];
    float*       out = (float*)d_out;

    int M = in_sizes[0] / IN_DIM;
    if (M > NODES_MAX) M = NODES_MAX;
    int E = in_sizes[1] / 2;

    // 128 blocks repack W1, last block detects index width.
    prep_kernel<<<129, 256>>>(W1, ei, E, M);

    dim3 ggrid(M_PAD / 64, 2);
    node_gemm_f16<<<ggrid, 256>>>(z, b1, M);

    edge_kernel<<<740, 256>>>(ei, W2, b2, out, E, M);
}

// round 16
// speedup vs baseline: 3.4535x; 1.0035x over previous
#include <cuda_runtime.h>
#include <cuda_fp16.h>
#include <cstdint>

#define NODES_MAX 100000
#define M_PAD 100096            // round up to 128
#define IN_DIM 128
#define HIDDEN 128

// Scratch (device globals: no allocations allowed).
__device__ __half g_Yh[(size_t)M_PAD * 256];     // per-node [A+b1 | B] features, fp16 (51 MB)
__device__ __half g_Wh[IN_DIM * 256];            // repacked W1 [k][o] fp16
__device__ int g_idx_is64;

// ---------------------------------------------------------------------------
// Fused prep: blocks [0,16) repack W1 -> Wh fp16 with COALESCED reads
// (thread walks k fastest; scatter moved to posted stores); last block
// detects index width (int64 vs int32 read as int64).
// ---------------------------------------------------------------------------
__global__ void prep_kernel(const float* __restrict__ W1,
                            const void* __restrict__ ei, int E, int M) {
    if (blockIdx.x == gridDim.x - 1) {
        __shared__ int bad;
        if (threadIdx.x == 0) bad = 0;
        __syncthreads();
        const long long* p = (const long long*)ei;
        int n = E < 512 ? E : 512;
        for (int i = threadIdx.x; i < n; i += blockDim.x) {
            long long v = p[i];
            if (v < 0 || v >= (long long)M) atomicOr(&bad, 1);
        }
        __syncthreads();
        if (threadIdx.x == 0) g_idx_is64 = bad ? 0 : 1;
        return;
    }
    // 16 blocks x 256 threads = 4096 threads; thread i -> o = i>>5 (row of W1),
    // k4 = (i&31)*4. Lanes of a warp share o and read consecutive float4s.
    int i = blockIdx.x * blockDim.x + threadIdx.x;
    int o = i >> 5;
    int k4 = (i & 31) * 4;
    float4 p0 = *(const float4*)(W1 + o * (2 * IN_DIM) + k4);            // src half
    float4 p1 = *(const float4*)(W1 + o * (2 * IN_DIM) + IN_DIM + k4);   // dst half
    float v0[4] = {p0.x, p0.y, p0.z, p0.w};
    float v1[4] = {p1.x, p1.y, p1.z, p1.w};
#pragma unroll
    for (int j = 0; j < 4; j++) {
        g_Wh[(k4 + j) * 256 + o] = __float2half_rn(v0[j]);
        g_Wh[(k4 + j) * 256 + 128 + o] = __float2half_rn(v1[j]);
    }
}

// ---------------------------------------------------------------------------
// GEMM helpers.
// ---------------------------------------------------------------------------
__device__ __forceinline__ void ldsm4(uint32_t* r, uint32_t addr) {
    asm volatile("ldmatrix.sync.aligned.m8n8.x4.shared.b16 {%0,%1,%2,%3}, [%4];"
                 : "=r"(r[0]), "=r"(r[1]), "=r"(r[2]), "=r"(r[3]) : "r"(addr));
}
__device__ __forceinline__ void ldsm4t(uint32_t* r, uint32_t addr) {
    asm volatile("ldmatrix.sync.aligned.m8n8.x4.trans.shared.b16 {%0,%1,%2,%3}, [%4];"
                 : "=r"(r[0]), "=r"(r[1]), "=r"(r[2]), "=r"(r[3]) : "r"(addr));
}
__device__ __forceinline__ void cp16(uint32_t saddr, const void* gptr) {
    asm volatile("cp.async.cg.shared.global [%0], [%1], 16;" :: "r"(saddr), "l"(gptr));
}
__device__ __forceinline__ void cp_commit() {
    asm volatile("cp.async.commit_group;");
}
template <int N> __device__ __forceinline__ void cp_wait() {
    asm volatile("cp.async.wait_group %0;" :: "n"(N));
}
__device__ __forceinline__ uint4 cvt8(float4 x, float4 y) {
    __half2 h0 = __floats2half2_rn(x.x, x.y);
    __half2 h1 = __floats2half2_rn(x.z, x.w);
    __half2 h2 = __floats2half2_rn(y.x, y.y);
    __half2 h3 = __floats2half2_rn(y.z, y.w);
    uint4 r;
    r.x = *(uint32_t*)&h0; r.y = *(uint32_t*)&h1;
    r.z = *(uint32_t*)&h2; r.w = *(uint32_t*)&h3;
    return r;
}
#define MMA16816(d, a, b)                                                      \
    asm volatile(                                                              \
        "mma.sync.aligned.m16n8k16.row.col.f32.f16.f16.f32 "                   \
        "{%0,%1,%2,%3}, {%4,%5,%6,%7}, {%8,%9}, {%0,%1,%2,%3};"                \
        : "+f"(d[0]), "+f"(d[1]), "+f"(d[2]), "+f"(d[3])                       \
        : "r"(a[0]), "r"(a[1]), "r"(a[2]), "r"(a[3]), "r"(b[0]), "r"(b[1]))

// ---------------------------------------------------------------------------
// Tensor-core GEMM with fused fp32->fp16 A conversion and fused b1 bias:
//   Yh[M x 256] = cvt(z)[M x 128] @ Wh[128 x 256]  (+ b1 on cols 0..127)
// Identical to validated R11/R13/R14 kernel.
// ---------------------------------------------------------------------------
#define STAGE_BYTES 12288

__global__ __launch_bounds__(256, 3) void node_gemm_f16(const float* __restrict__ z,
                                                        const float* __restrict__ b1,
                                                        int M) {
    __shared__ __align__(16) unsigned char smem[4 * STAGE_BYTES];

    const int tid = threadIdx.x;
    const int lane = tid & 31;
    const int w = tid >> 5;
    const int wm = w & 1;          // 2 warps along M (32 rows each)
    const int wn = w >> 1;         // 4 warps along N (32 cols each)
    const int row0 = blockIdx.x * 64;
    const int col0 = blockIdx.y * 128;

    const uint32_t sbase = (uint32_t)__cvta_generic_to_shared(&smem[0]);

    // ---- B async store mapping ----
    const int bk = tid >> 3;
    const int bs = tid & 7;
    const uint32_t sB0 = sbase + 4096 + bk * 256 + (((bs) << 4) ^ ((bk & 7) << 4));
    const uint32_t sB1 = sbase + 4096 + bk * 256 + (((bs + 8) << 4) ^ ((bk & 7) << 4));
    const __half* BgBase = g_Wh + (size_t)bk * 256 + col0 + bs * 8;

#pragma unroll
    for (int c = 0; c < 4; c++) {
        uint32_t st = c * STAGE_BYTES;
        cp16(sB0 + st, BgBase + (size_t)c * 32 * 256);
        cp16(sB1 + st, BgBase + (size_t)c * 32 * 256 + 64);
        cp_commit();
    }

    // ---- A store mapping: row=tid>>2, 16B slot=tid&3 ----
    const int ar = tid >> 2;
    const int as = tid & 3;
    const int aByte = ar * 64 + (((as) ^ ((ar >> 1) & 3)) << 4);
    const int arow = row0 + ar;
    const float* Az = z + (size_t)(arow < M ? arow : 0) * 128 + as * 8;

    float4 rfa, rfb;
    rfa = *(const float4*)(Az);          // chunk 0
    rfb = *(const float4*)(Az + 4);
    *(uint4*)(&smem[0 * STAGE_BYTES + aByte]) = cvt8(rfa, rfb);
    rfa = *(const float4*)(Az + 32);     // chunk 1
    rfb = *(const float4*)(Az + 36);

    // ---- ldmatrix per-thread offsets (within a stage) ----
    uint32_t aOff[2];
#pragma unroll
    for (int mi = 0; mi < 2; mi++) {
        int r = wm * 32 + mi * 16 + (lane & 15);
        int slot = (lane >> 4) ^ ((r >> 1) & 3);
        aOff[mi] = r * 64 + slot * 16;              // kk=1 -> ^0x20
    }
    uint32_t bOff[2];
    {
        int k = lane & 15;
#pragma unroll
        for (int ni = 0; ni < 2; ni++) {
            int nb = wn * 64 + ni * 32 + ((lane >> 4) & 1) * 16;
            bOff[ni] = 4096 + k * 256 + (nb ^ ((k & 7) << 4));  // kk=1 -> +4096
        }
    }

    float acc[2][4][4];
#pragma unroll
    for (int i = 0; i < 2; i++)
#pragma unroll
        for (int j = 0; j < 4; j++)
#pragma unroll
            for (int t = 0; t < 4; t++) acc[i][j][t] = 0.0f;

#define CHUNK(c)                                                               \
    {                                                                          \
        cp_wait<3 - (c)>();                                                    \
        __syncthreads();                                                       \
        if ((c) < 3) {                                                         \
            *(uint4*)(&smem[((c) + 1) * STAGE_BYTES + aByte]) = cvt8(rfa, rfb);\
            if ((c) < 2) {                                                     \
                rfa = *(const float4*)(Az + ((c) + 2) * 32);                   \
                rfb = *(const float4*)(Az + ((c) + 2) * 32 + 4);               \
            }                                                                  \
        }                                                                      \
        const uint32_t buf = sbase + (c) * STAGE_BYTES;                        \
        _Pragma("unroll")                                                      \
        for (int kk = 0; kk < 2; kk++) {                                       \
            uint32_t a[2][4], b[4][2];                                         \
            _Pragma("unroll")                                                  \
            for (int mi = 0; mi < 2; mi++)                                     \
                ldsm4(a[mi], buf + (kk ? (aOff[mi] ^ 0x20) : aOff[mi]));       \
            _Pragma("unroll")                                                  \
            for (int ni = 0; ni < 2; ni++) {                                   \
                uint32_t r[4];                                                 \
                ldsm4t(r, buf + bOff[ni] + (kk ? 4096 : 0));                   \
                b[ni * 2 + 0][0] = r[0]; b[ni * 2 + 0][1] = r[1];              \
                b[ni * 2 + 1][0] = r[2]; b[ni * 2 + 1][1] = r[3];              \
            }                                                                  \
            _Pragma("unroll")                                                  \
            for (int mi = 0; mi < 2; mi++)                                     \
                _Pragma("unroll")                                              \
                for (int ni = 0; ni < 4; ni++)                                 \
                    MMA16816(acc[mi][ni], a[mi], b[ni]);                       \
        }                                                                      \
    }

    CHUNK(0)
    CHUNK(1)
    CHUNK(2)
    CHUNK(3)
#undef CHUNK

    // epilogue: fp32 acc (+ b1 on the src half, i.e. blockIdx.y==0) -> fp16 Y
    const int tr = lane >> 2;
    const int tc = (lane & 3) * 2;
    float2 bias[4];
#pragma unroll
    for (int ni = 0; ni < 4; ni++) {
        if (col0 == 0) {
            bias[ni] = *(const float2*)(b1 + wn * 32 + ni * 8 + tc);
        } else {
            bias[ni] = make_float2(0.f, 0.f);
        }
    }
#pragma unroll
    for (int mi = 0; mi < 2; mi++) {
#pragma unroll
        for (int ni = 0; ni < 4; ni++) {
            int gr = row0 + wm * 32 + mi * 16 + tr;
            int gc = col0 + wn * 32 + ni * 8 + tc;
            if (gr < M) {
                __half2 v0 = __floats2half2_rn(acc[mi][ni][0] + bias[ni].x,
                                               acc[mi][ni][1] + bias[ni].y);
                *(__half2*)(g_Yh + (size_t)gr * 256 + gc) = v0;
            }
            if (gr + 8 < M) {
                __half2 v1 = __floats2half2_rn(acc[mi][ni][2] + bias[ni].x,
                                               acc[mi][ni][3] + bias[ni].y);
                *(__half2*)(g_Yh + (size_t)(gr + 8) * 256 + gc) = v1;
            }
        }
    }
}

// ---------------------------------------------------------------------------
// Per-edge stage v6 (identical to validated R14): 8 lanes per edge,
// W2 packed as 8x half2, __launch_bounds__(256,5) for 40 warps/SM.
// ---------------------------------------------------------------------------
__global__ __launch_bounds__(256, 5) void edge_kernel(
        const void* __restrict__ ei,
        const float* __restrict__ W2,
        const float* __restrict__ b2,
        float* __restrict__ out, int E, int M) {
    const int lane = threadIdx.x & 31;
    const int octet = lane >> 3;      // which edge of the 4 in the warp
    const int oi = lane & 7;          // unit group within the edge

    int gw = (blockIdx.x * blockDim.x + threadIdx.x) >> 5;
    const int nw = (gridDim.x * blockDim.x) >> 5;

    // Per-lane W2 slice: units [16*oi, 16*oi+16), packed as 8 half2.
    __half2 w2h[8];
#pragma unroll
    for (int j = 0; j < 4; j++) {
        float4 t = *(const float4*)(W2 + oi * 16 + j * 4);
        w2h[j * 2 + 0] = __floats2half2_rn(t.x, t.y);
        w2h[j * 2 + 1] = __floats2half2_rn(t.z, t.w);
    }
    const float pp0 = b2[0] * 0.125f;   // b2 distributed over 8 lanes (exact /8)
    const int is64 = g_idx_is64;
    const __half2 z2 = __float2half2_rn(0.0f);

    const long long* __restrict__ src64 = (const long long*)ei;
    const long long* __restrict__ dst64 = src64 + E;
    const int* __restrict__ src32 = (const int*)ei;
    const int* __restrict__ dst32 = src32 + E;

    for (int e0 = gw * 8; e0 < E; e0 += nw * 8) {
        // group g handles edge e0 + g*4 + octet
        int s[2], d[2], ee[2];
#pragma unroll
        for (int g = 0; g < 2; g++) {
            int e = e0 + g * 4 + octet;
            ee[g] = e;
            if (e >= E) e = E - 1;
            int ss, dd;
            if (is64) { ss = (int)src64[e]; dd = (int)dst64[e]; }
            else      { ss = src32[e];      dd = dst32[e]; }
            if ((unsigned)ss >= (unsigned)M) ss = 0;
            if ((unsigned)dd >= (unsigned)M) dd = 0;
            s[g] = ss; d[g] = dd;
        }

        // Issue all 8 gathers before any compute.
        uint4 va[2][2], vb[2][2];
#pragma unroll
        for (int g = 0; g < 2; g++) {
            const __half* ps = g_Yh + (size_t)s[g] * 256 + oi * 16;
            const __half* pd = g_Yh + (size_t)d[g] * 256 + 128 + oi * 16;
            va[g][0] = *(const uint4*)(ps);
            va[g][1] = *(const uint4*)(ps + 8);
            vb[g][0] = *(const uint4*)(pd);
            vb[g][1] = *(const uint4*)(pd + 8);
        }

#pragma unroll
        for (int g = 0; g < 2; g++) {
            float pp = pp0;
            const uint32_t* ua = (const uint32_t*)&va[g][0];
            const uint32_t* ub = (const uint32_t*)&vb[g][0];
#pragma unroll
            for (int j = 0; j < 8; j++) {
                __half2 h = __hmax2(__hadd2(*(const __half2*)&ua[j],
                                            *(const __half2*)&ub[j]), z2);
                float2 f = __half22float2(h);
                float2 wf = __half22float2(w2h[j]);
                pp = fmaf(f.x, wf.x, pp);
                pp = fmaf(f.y, wf.y, pp);
            }
            // butterfly over the octet (offsets 4,2,1 stay within 8 lanes)
            pp += __shfl_xor_sync(0xffffffffu, pp, 4);
            pp += __shfl_xor_sync(0xffffffffu, pp, 2);
            pp += __shfl_xor_sync(0xffffffffu, pp, 1);

            if (oi == 0 && ee[g] < E) out[ee[g]] = pp;
        }
    }
}

// ---------------------------------------------------------------------------
extern "C" void kernel_launch(void* const* d_in, const int* in_sizes, int n_in,
                              void* d_out, int out_size) {
    const float* z  = (const float*)d_in[0];
    const void*  ei = d_in[1];
    const float* W1 = (const float*)d_in[2];
    const float* b1 = (const float*)d_in[3];
    const float* W2 = (const float*)d_in[4];
    const float* b2 = (const float*)d_in[5];
    float*       out = (float*)d_out;

    int M = in_sizes[0] / IN_DIM;
    if (M > NODES_MAX) M = NODES_MAX;
    int E = in_sizes[1] / 2;

    // 16 blocks repack W1 (coalesced reads), last block detects index width.
    prep_kernel<<<17, 256>>>(W1, ei, E, M);

    dim3 ggrid(M_PAD / 64, 2);
    node_gemm_f16<<<ggrid, 256>>>(z, b1, M);

    edge_kernel<<<740, 256>>>(ei, W2, b2, out, E, M);
}